// round 11
// baseline (speedup 1.0000x reference)
#include <cuda_runtime.h>
#include <cuda_fp16.h>
#include <cstdint>

#define TPB 256
#define NWARP 8
#define TILE_E (NWARP * 32)
#define EGRID 304
#define MAXN 50000

// Per-node precomputed projections in FP16, COLUMN-PERMUTED:
// slice0 [0:32)  = nf@We1[0:128]+be1 (src)
// slice1 [32:64) = nf@We1[128:256]   (dst)
// slice2 [64:128)= nf@Wn1[0:128]+bn1 (pre2)
__device__ __align__(16) __half g_P[MAXN * 128];

// ------------------------------- helpers ----------------------------------
__device__ __forceinline__ uint32_t h2pack(float lo, float hi) {
    uint32_t r;  // cvt.rn.f16x2.f32 d, a, b -> d.hi = a, d.lo = b
    asm("cvt.rn.f16x2.f32 %0, %1, %2;" : "=r"(r) : "f"(hi), "f"(lo));
    return r;
}
__device__ __forceinline__ uint32_t h2relu(float c0, float c1) {
    return h2pack(fmaxf(c0, 0.f), fmaxf(c1, 0.f));
}
__device__ __forceinline__ void red4(float* p, float a, float b, float c, float d) {
    asm volatile("red.global.add.v4.f32 [%0], {%1,%2,%3,%4};"
                 :: "l"(p), "f"(a), "f"(b), "f"(c), "f"(d) : "memory");
}
// D(16x8,f32) += A(16x16,f16) @ B(16x8,f16)
__device__ __forceinline__ void mma16(float* c, uint32_t a0, uint32_t a1,
                                      uint32_t a2, uint32_t a3,
                                      uint32_t b0, uint32_t b1) {
    asm volatile("mma.sync.aligned.m16n8k16.row.col.f32.f16.f16.f32 "
                 "{%0,%1,%2,%3}, {%4,%5,%6,%7}, {%8,%9}, {%0,%1,%2,%3};"
                 : "+f"(c[0]), "+f"(c[1]), "+f"(c[2]), "+f"(c[3])
                 : "r"(a0), "r"(a1), "r"(a2), "r"(a3), "r"(b0), "r"(b1));
}

// ---------------------------------------------------------------------------
// Precompute via mma16: P = [nf@We1_src+be1 | nf@We1_dst | nf@Wn1_dst+bn1]
// 16 nodes per warp (full m16 tile), 128 nodes per CTA -> fine-grained waves.
// out=nf init handled by cudaMemcpyAsync in the launcher.
// ---------------------------------------------------------------------------
#define P_TPB 256
#define P_WSMEM 4352                 // per-warp nf buffer [16][68] words
#define P_OFF_B 34816                // bias after Wp [128][68] words
#define P_OFF_SCR 35328
#define P_SMEM (P_OFF_SCR + 8 * P_WSMEM)   // 70144

__global__ void __launch_bounds__(P_TPB, 1) precompute_mma_kernel(
    const float* __restrict__ nf,
    const float* __restrict__ We1,
    const float* __restrict__ be1,
    const float* __restrict__ Wn1,
    const float* __restrict__ bn1,
    int Nn)
{
    extern __shared__ char sm[];
    uint32_t* Wp = (uint32_t*)sm;                 // [128 n][68 w] f16x2
    float* bias  = (float*)(sm + P_OFF_B);        // [128]

    const int tid = threadIdx.x;
    for (int i = tid; i < 128 * 64; i += P_TPB) {
        int n = i >> 6, w = i & 63;
        float lo, hi;
        if (n < 32)      { lo = We1[(2*w)*32 + n];         hi = We1[(2*w+1)*32 + n]; }
        else if (n < 64) { lo = We1[(128+2*w)*32 + n-32];  hi = We1[(128+2*w+1)*32 + n-32]; }
        else             { lo = Wn1[(2*w)*64 + n-64];      hi = Wn1[(2*w+1)*64 + n-64]; }
        Wp[n*68 + w] = h2pack(lo, hi);
    }
    if (tid < 128)
        bias[tid] = (tid < 32) ? be1[tid] : ((tid < 64) ? 0.f : bn1[tid - 64]);
    __syncthreads();

    const int lane = tid & 31, wid = tid >> 5;
    const int g = lane >> 2, q = lane & 3;
    uint32_t* buf = (uint32_t*)(sm + P_OFF_SCR + wid * P_WSMEM);   // [16][68]

    const int nb = blockIdx.x * 128 + wid * 16;

    // stage 16 nf rows (f32->f16x2); one row per iteration, 32 lanes x float4
    #pragma unroll
    for (int row = 0; row < 16; row++) {
        int n = nb + row;
        if (n < Nn) {
            float4 v = *(const float4*)&nf[(size_t)n * 128 + 4 * lane];
            uint2 w = { h2pack(v.x, v.y), h2pack(v.z, v.w) };
            *(uint2*)&buf[row * 68 + 2 * lane] = w;
        } else {
            *(uint2*)&buf[row * 68 + 2 * lane] = make_uint2(0, 0);
        }
    }
    __syncwarp();

    float c[16][4];
    #pragma unroll
    for (int nt = 0; nt < 16; nt++) {
        float2 b = *(const float2*)&bias[8 * nt + 2 * q];
        c[nt][0] = b.x; c[nt][1] = b.y;
        c[nt][2] = b.x; c[nt][3] = b.y;
    }
    #pragma unroll
    for (int kt = 0; kt < 8; kt++) {
        int r0 = g * 68, r1 = (8 + g) * 68;
        uint32_t a0 = buf[r0 + 8*kt + q];
        uint32_t a1 = buf[r1 + 8*kt + q];
        uint32_t a2 = buf[r0 + 8*kt + q + 4];
        uint32_t a3 = buf[r1 + 8*kt + q + 4];
        #pragma unroll
        for (int nt = 0; nt < 16; nt++) {
            uint32_t b0 = Wp[(8*nt+g)*68 + 8*kt + q];
            uint32_t b1 = Wp[(8*nt+g)*68 + 8*kt + q + 4];
            mma16(c[nt], a0, a1, a2, a3, b0, b1);
        }
    }
    // store permuted f16 pairs
    #pragma unroll
    for (int nt = 0; nt < 16; nt++) {
        int word = (nt < 4)  ? (q*4 + nt)
                 : (nt < 8)  ? (16 + q*4 + (nt - 4))
                 :             (32 + q*8 + (nt - 8));
        int n0 = nb + g, n1 = nb + 8 + g;
        if (n0 < Nn)
            ((uint32_t*)&g_P[(size_t)n0 * 128])[word] = h2pack(c[nt][0], c[nt][1]);
        if (n1 < Nn)
            ((uint32_t*)&g_P[(size_t)n1 * 128])[word] = h2pack(c[nt][2], c[nt][3]);
    }
}

// ---------------------------------------------------------------------------
// Edge kernel: persistent, 8 warps x 32 edges, 2 CTAs/SM. mma.sync FP16.
// h1/em/h2 all pass layer-to-layer via in-register C->A packing; smem buf
// used only for ef staging and the scatter transpose.
// ---------------------------------------------------------------------------
#define OFF_W1  0            // [32 n][36 w]  -> 4608 B
#define OFF_W2  4608         // [128][20]     -> 10240 B
#define OFF_W3  14848        // [64][68]      -> 17408 B
#define OFF_W4  32256        // [128][36]     -> 18432 B
#define OFF_BE2 50688
#define OFF_BN2 51200
#define OFF_SCR 51712
#define WS_BYTES 4608        // per-warp buffer (ef f16 / nm f32)
#define SM_TOTAL (OFF_SCR + NWARP * WS_BYTES)   // 88576

__global__ void __launch_bounds__(TPB, 2) edge_mma_kernel(
    const float* __restrict__ ef,
    const int*   __restrict__ eidx,
    const float* __restrict__ We1,
    const float* __restrict__ We2,
    const float* __restrict__ be2,
    const float* __restrict__ Wn1,
    const float* __restrict__ Wn2,
    const float* __restrict__ bn2,
    float* __restrict__ out, int E, int ntiles)
{
    extern __shared__ char sm[];
    uint32_t* W1s = (uint32_t*)(sm + OFF_W1);
    uint32_t* W2s = (uint32_t*)(sm + OFF_W2);
    uint32_t* W3s = (uint32_t*)(sm + OFF_W3);
    uint32_t* W4s = (uint32_t*)(sm + OFF_W4);
    float* be2s = (float*)(sm + OFF_BE2);
    float* bn2s = (float*)(sm + OFF_BN2);

    const int tid = threadIdx.x;
    {
        const float* W = We1 + 256 * 32;
        for (int i = tid; i < 32 * 32; i += TPB) {
            int n = i >> 5, w = i & 31;
            W1s[n*36 + w] = h2pack(W[(2*w)*32 + n], W[(2*w+1)*32 + n]);
        }
        for (int i = tid; i < 128 * 16; i += TPB) {
            int n = i >> 4, w = i & 15;
            W2s[n*20 + w] = h2pack(We2[(2*w)*128 + n], We2[(2*w+1)*128 + n]);
        }
        const float* W3 = Wn1 + 128 * 64;
        for (int i = tid; i < 64 * 64; i += TPB) {
            int n = i >> 6, w = i & 63;
            W3s[n*68 + w] = h2pack(W3[(2*w)*64 + n], W3[(2*w+1)*64 + n]);
        }
        for (int i = tid; i < 128 * 32; i += TPB) {
            int n = i >> 5, w = i & 31;
            W4s[n*36 + w] = h2pack(Wn2[(2*w)*128 + n], Wn2[(2*w+1)*128 + n]);
        }
    }
    if (tid < 128) { be2s[tid] = be2[tid]; bn2s[tid] = bn2[tid]; }
    __syncthreads();

    const int lane = tid & 31, wid = tid >> 5;
    const int g = lane >> 2, q = lane & 3;
    const unsigned F = 0xFFFFFFFFu;
    uint32_t* buf  = (uint32_t*)(sm + OFF_SCR + wid * WS_BYTES);
    float*    buff = (float*)buf;

    for (int t = blockIdx.x; t < ntiles; t += gridDim.x) {
        const int eb = t * TILE_E + wid * 32;

        int sidx[4], didx[4];
        #pragma unroll
        for (int m = 0; m < 4; m++) {
            int r = eb + 16 * (m >> 1) + 8 * (m & 1) + g;
            r = (r < E) ? r : (E - 1);
            sidx[m] = eidx[r];
            didx[m] = eidx[E + r];
        }
        int rl = eb + lane; rl = (rl < E) ? rl : (E - 1);
        const int dl = eidx[E + rl];

        // ======== L1 init: c1 = pre1 =======================================
        float c1[2][4][4];
        #pragma unroll
        for (int m = 0; m < 4; m++) {
            const int mt = m >> 1, h = m & 1;
            uint4 us = *(const uint4*)&g_P[(size_t)sidx[m] * 128 + q * 8];
            uint4 ud = *(const uint4*)&g_P[(size_t)didx[m] * 128 + 32 + q * 8];
            const uint32_t* sw = (const uint32_t*)&us;
            const uint32_t* dw = (const uint32_t*)&ud;
            #pragma unroll
            for (int nt = 0; nt < 4; nt++) {
                float2 a = __half22float2(*(const __half2*)&sw[nt]);
                float2 b = __half22float2(*(const __half2*)&dw[nt]);
                c1[mt][nt][2*h]   = a.x + b.x;
                c1[mt][nt][2*h+1] = a.y + b.y;
            }
        }

        // ======== stage ef =================================================
        __syncwarp();
        #pragma unroll
        for (int i = 0; i < 16; i++) {
            int idx = i * 32 + lane;
            int row = idx >> 4, c16 = idx & 15;
            int r = eb + row; r = (r < E) ? r : (E - 1);
            float4 v = *(const float4*)&ef[(size_t)r * 64 + 4 * c16];
            uint2 w = { h2pack(v.x, v.y), h2pack(v.z, v.w) };
            *(uint2*)&buf[row * 36 + 2 * c16] = w;
        }
        __syncwarp();

        // ======== L1: K=64 -> 4 k16 chunks =================================
        #pragma unroll
        for (int kt = 0; kt < 4; kt++) {
            uint32_t a[2][4];
            #pragma unroll
            for (int mt = 0; mt < 2; mt++) {
                int r0 = (16*mt + g) * 36, r1 = (16*mt + 8 + g) * 36;
                a[mt][0] = buf[r0 + 8*kt + q];
                a[mt][1] = buf[r1 + 8*kt + q];
                a[mt][2] = buf[r0 + 8*kt + q + 4];
                a[mt][3] = buf[r1 + 8*kt + q + 4];
            }
            #pragma unroll
            for (int nt = 0; nt < 4; nt++) {
                uint32_t b0 = W1s[(8*nt+g)*36 + 8*kt + q];
                uint32_t b1 = W1s[(8*nt+g)*36 + 8*kt + q + 4];
                mma16(c1[0][nt], a[0][0],a[0][1],a[0][2],a[0][3], b0, b1);
                mma16(c1[1][nt], a[1][0],a[1][1],a[1][2],a[1][3], b0, b1);
            }
        }
        // ---- h1 C->A local packing (NO smem roundtrip) --------------------
        uint32_t h1a[2][2][4];
        #pragma unroll
        for (int kc = 0; kc < 2; kc++)
            #pragma unroll
            for (int mt = 0; mt < 2; mt++) {
                h1a[kc][mt][0] = h2relu(c1[mt][2*kc][0],   c1[mt][2*kc][1]);
                h1a[kc][mt][1] = h2relu(c1[mt][2*kc][2],   c1[mt][2*kc][3]);
                h1a[kc][mt][2] = h2relu(c1[mt][2*kc+1][0], c1[mt][2*kc+1][1]);
                h1a[kc][mt][3] = h2relu(c1[mt][2*kc+1][2], c1[mt][2*kc+1][3]);
            }

        // ========== L2+L3 fused ============================================
        float c3[2][8][4];
        #pragma unroll
        for (int m = 0; m < 4; m++) {
            const int mt = m >> 1, h = m & 1;
            const __half* Pp = &g_P[(size_t)didx[m] * 128 + 64 + q * 16];
            uint4 p0 = *(const uint4*)Pp;
            uint4 p1 = *(const uint4*)(Pp + 8);
            const uint32_t* w0 = (const uint32_t*)&p0;
            const uint32_t* w1 = (const uint32_t*)&p1;
            #pragma unroll
            for (int nt = 0; nt < 4; nt++) {
                float2 a = __half22float2(*(const __half2*)&w0[nt]);
                float2 b = __half22float2(*(const __half2*)&w1[nt]);
                c3[mt][nt][2*h]   = a.x;  c3[mt][nt][2*h+1]   = a.y;
                c3[mt][nt+4][2*h] = b.x;  c3[mt][nt+4][2*h+1] = b.y;
            }
        }
        #pragma unroll
        for (int ch = 0; ch < 4; ch++) {
            float c2[2][4][4];
            #pragma unroll
            for (int nt = 0; nt < 4; nt++) {
                float2 b = *(const float2*)&be2s[32*ch + 8*nt + 2*q];
                #pragma unroll
                for (int mt = 0; mt < 2; mt++) {
                    c2[mt][nt][0] = b.x; c2[mt][nt][1] = b.y;
                    c2[mt][nt][2] = b.x; c2[mt][nt][3] = b.y;
                }
            }
            #pragma unroll
            for (int kt = 0; kt < 2; kt++) {
                #pragma unroll
                for (int nt = 0; nt < 4; nt++) {
                    uint32_t b0 = W2s[(32*ch + 8*nt + g)*20 + 8*kt + q];
                    uint32_t b1 = W2s[(32*ch + 8*nt + g)*20 + 8*kt + q + 4];
                    mma16(c2[0][nt], h1a[kt][0][0],h1a[kt][0][1],h1a[kt][0][2],h1a[kt][0][3], b0, b1);
                    mma16(c2[1][nt], h1a[kt][1][0],h1a[kt][1][1],h1a[kt][1][2],h1a[kt][1][3], b0, b1);
                }
            }
            #pragma unroll
            for (int kc = 0; kc < 2; kc++) {
                uint32_t a[2][4];
                #pragma unroll
                for (int mt = 0; mt < 2; mt++) {
                    a[mt][0] = h2relu(c2[mt][2*kc][0],   c2[mt][2*kc][1]);
                    a[mt][1] = h2relu(c2[mt][2*kc][2],   c2[mt][2*kc][3]);
                    a[mt][2] = h2relu(c2[mt][2*kc+1][0], c2[mt][2*kc+1][1]);
                    a[mt][3] = h2relu(c2[mt][2*kc+1][2], c2[mt][2*kc+1][3]);
                }
                const int ktg = 2 * ch + kc;
                #pragma unroll
                for (int nt = 0; nt < 8; nt++) {
                    uint32_t b0 = W3s[(8*nt+g)*68 + 8*ktg + q];
                    uint32_t b1 = W3s[(8*nt+g)*68 + 8*ktg + q + 4];
                    mma16(c3[0][nt], a[0][0],a[0][1],a[0][2],a[0][3], b0, b1);
                    mma16(c3[1][nt], a[1][0],a[1][1],a[1][2],a[1][3], b0, b1);
                }
            }
        }

        // ---- h2 C->A local packing ----------------------------------------
        uint32_t h2a[4][2][4];
        #pragma unroll
        for (int kc = 0; kc < 4; kc++)
            #pragma unroll
            for (int mt = 0; mt < 2; mt++) {
                h2a[kc][mt][0] = h2relu(c3[mt][2*kc][0],   c3[mt][2*kc][1]);
                h2a[kc][mt][1] = h2relu(c3[mt][2*kc][2],   c3[mt][2*kc][3]);
                h2a[kc][mt][2] = h2relu(c3[mt][2*kc+1][0], c3[mt][2*kc+1][1]);
                h2a[kc][mt][3] = h2relu(c3[mt][2*kc+1][2], c3[mt][2*kc+1][3]);
            }

        // ============ L4 + smem transpose + coalesced red4 scatter =========
        #pragma unroll
        for (int n4 = 0; n4 < 4; n4++) {
            float c4[2][4][4];
            #pragma unroll
            for (int nt = 0; nt < 4; nt++) {
                float2 b = *(const float2*)&bn2s[32*n4 + 8*nt + 2*q];
                #pragma unroll
                for (int mt = 0; mt < 2; mt++) {
                    c4[mt][nt][0] = b.x; c4[mt][nt][1] = b.y;
                    c4[mt][nt][2] = b.x; c4[mt][nt][3] = b.y;
                }
            }
            #pragma unroll
            for (int kt = 0; kt < 4; kt++) {
                #pragma unroll
                for (int nt = 0; nt < 4; nt++) {
                    uint32_t b0 = W4s[(32*n4 + 8*nt + g)*36 + 8*kt + q];
                    uint32_t b1 = W4s[(32*n4 + 8*nt + g)*36 + 8*kt + q + 4];
                    mma16(c4[0][nt], h2a[kt][0][0],h2a[kt][0][1],h2a[kt][0][2],h2a[kt][0][3], b0, b1);
                    mma16(c4[1][nt], h2a[kt][1][0],h2a[kt][1][1],h2a[kt][1][2],h2a[kt][1][3], b0, b1);
                }
            }
            __syncwarp();
            #pragma unroll
            for (int mt = 0; mt < 2; mt++)
                #pragma unroll
                for (int nt = 0; nt < 4; nt++) {
                    const int col = 8 * nt + 2 * q;
                    float2 v0 = { fmaxf(c4[mt][nt][0], 0.f), fmaxf(c4[mt][nt][1], 0.f) };
                    float2 v1 = { fmaxf(c4[mt][nt][2], 0.f), fmaxf(c4[mt][nt][3], 0.f) };
                    *(float2*)&buff[(16*mt + g) * 36 + col]     = v0;
                    *(float2*)&buff[(16*mt + 8 + g) * 36 + col] = v1;
                }
            __syncwarp();
            #pragma unroll
            for (int i = 0; i < 8; i++) {
                int row = 4 * i + (lane >> 3);
                float4 v = *(const float4*)&buff[row * 36 + 4 * (lane & 7)];
                int dr = __shfl_sync(F, dl, row);
                if (eb + row < E)
                    red4(out + (size_t)dr * 128 + 32 * n4 + 4 * (lane & 7),
                         v.x, v.y, v.z, v.w);
            }
        }
    }
}

// ---------------------------------------------------------------------------
extern "C" void kernel_launch(void* const* d_in, const int* in_sizes, int n_in,
                              void* d_out, int out_size) {
    const float* nf  = (const float*)d_in[0];
    const float* ef  = (const float*)d_in[1];
    const int*   ei  = (const int*)  d_in[2];
    const float* We1 = (const float*)d_in[3];
    const float* be1 = (const float*)d_in[4];
    const float* We2 = (const float*)d_in[5];
    const float* be2 = (const float*)d_in[6];
    const float* Wn1 = (const float*)d_in[7];
    const float* bn1 = (const float*)d_in[8];
    const float* Wn2 = (const float*)d_in[9];
    const float* bn2 = (const float*)d_in[10];
    float* out = (float*)d_out;

    const int Nn = in_sizes[0] / 128;
    const int E  = in_sizes[2] / 2;
    const int ntiles = (E + TILE_E - 1) / TILE_E;

    // out = node_features via copy engine (graph-capturable D2D async copy)
    cudaMemcpyAsync(out, nf, (size_t)Nn * 128 * sizeof(float),
                    cudaMemcpyDeviceToDevice, 0);

    cudaFuncSetAttribute(precompute_mma_kernel,
                         cudaFuncAttributeMaxDynamicSharedMemorySize, P_SMEM);
    precompute_mma_kernel<<<(Nn + 127) / 128, P_TPB, P_SMEM>>>(
        nf, We1, be1, Wn1, bn1, Nn);

    cudaFuncSetAttribute(edge_mma_kernel,
                         cudaFuncAttributeMaxDynamicSharedMemorySize, SM_TOTAL);
    edge_mma_kernel<<<EGRID, TPB, SM_TOTAL>>>(ef, ei, We1, We2, be2,
                                              Wn1, Wn2, bn2, out, E, ntiles);
}

// round 12
// speedup vs baseline: 1.0242x; 1.0242x over previous
#include <cuda_runtime.h>
#include <cuda_fp16.h>
#include <cstdint>

#define TPB 256
#define NWARP 8
#define TILE_E (NWARP * 32)
#define EGRID 304
#define MAXN 50000

// Per-node precomputed projections in FP16, COLUMN-PERMUTED:
// slice0 [0:32)  = nf@We1[0:128]+be1 (src)
// slice1 [32:64) = nf@We1[128:256]   (dst)
// slice2 [64:128)= nf@Wn1[0:128]+bn1 (pre2)
__device__ __align__(16) __half g_P[MAXN * 128];

// ------------------------------- helpers ----------------------------------
__device__ __forceinline__ uint32_t h2pack(float lo, float hi) {
    uint32_t r;  // cvt.rn.f16x2.f32 d, a, b -> d.hi = a, d.lo = b
    asm("cvt.rn.f16x2.f32 %0, %1, %2;" : "=r"(r) : "f"(hi), "f"(lo));
    return r;
}
__device__ __forceinline__ uint32_t h2relu(float c0, float c1) {
    return h2pack(fmaxf(c0, 0.f), fmaxf(c1, 0.f));
}
__device__ __forceinline__ void red4(float* p, float a, float b, float c, float d) {
    asm volatile("red.global.add.v4.f32 [%0], {%1,%2,%3,%4};"
                 :: "l"(p), "f"(a), "f"(b), "f"(c), "f"(d) : "memory");
}
// D(16x8,f32) += A(16x16,f16) @ B(16x8,f16)
__device__ __forceinline__ void mma16(float* c, uint32_t a0, uint32_t a1,
                                      uint32_t a2, uint32_t a3,
                                      uint32_t b0, uint32_t b1) {
    asm volatile("mma.sync.aligned.m16n8k16.row.col.f32.f16.f16.f32 "
                 "{%0,%1,%2,%3}, {%4,%5,%6,%7}, {%8,%9}, {%0,%1,%2,%3};"
                 : "+f"(c[0]), "+f"(c[1]), "+f"(c[2]), "+f"(c[3])
                 : "r"(a0), "r"(a1), "r"(a2), "r"(a3), "r"(b0), "r"(b1));
}

// ---------------------------------------------------------------------------
// Precompute via mma16 (R10 version): 32 nodes/warp, 256 nodes/CTA.
// Fused out = node_features copy in the nf staging pass.
// ---------------------------------------------------------------------------
#define P_TPB 256
#define P_WSMEM 8704                 // per-warp nf buffer [32][68] words
#define P_OFF_B 34816                // bias after Wp [128][68] words
#define P_OFF_SCR 35328
#define P_SMEM (P_OFF_SCR + 8 * P_WSMEM)   // 104960

__global__ void __launch_bounds__(P_TPB, 1) precompute_mma_kernel(
    const float* __restrict__ nf,
    const float* __restrict__ We1,
    const float* __restrict__ be1,
    const float* __restrict__ Wn1,
    const float* __restrict__ bn1,
    float* __restrict__ out, int Nn)
{
    extern __shared__ char sm[];
    uint32_t* Wp = (uint32_t*)sm;                 // [128 n][68 w] f16x2
    float* bias  = (float*)(sm + P_OFF_B);        // [128]

    const int tid = threadIdx.x;
    for (int i = tid; i < 128 * 64; i += P_TPB) {
        int n = i >> 6, w = i & 63;
        float lo, hi;
        if (n < 32)      { lo = We1[(2*w)*32 + n];         hi = We1[(2*w+1)*32 + n]; }
        else if (n < 64) { lo = We1[(128+2*w)*32 + n-32];  hi = We1[(128+2*w+1)*32 + n-32]; }
        else             { lo = Wn1[(2*w)*64 + n-64];      hi = Wn1[(2*w+1)*64 + n-64]; }
        Wp[n*68 + w] = h2pack(lo, hi);
    }
    if (tid < 128)
        bias[tid] = (tid < 32) ? be1[tid] : ((tid < 64) ? 0.f : bn1[tid - 64]);
    __syncthreads();

    const int lane = tid & 31, wid = tid >> 5;
    const int g = lane >> 2, q = lane & 3;
    uint32_t* buf = (uint32_t*)(sm + P_OFF_SCR + wid * P_WSMEM);   // [32][68]

    const int nb = blockIdx.x * 256 + wid * 32;

    // stage nf rows (f32->f16x2) + fused out=nf copy
    #pragma unroll
    for (int it = 0; it < 32; it++) {
        int idx = it * 32 + lane;
        int row = idx >> 5, c = idx & 31;
        int n = nb + row;
        if (n < Nn) {
            float4 v = *(const float4*)&nf[(size_t)n * 128 + 4 * c];
            *(float4*)&out[(size_t)n * 128 + 4 * c] = v;
            uint2 w = { h2pack(v.x, v.y), h2pack(v.z, v.w) };
            *(uint2*)&buf[row * 68 + 2 * c] = w;
        } else {
            *(uint2*)&buf[row * 68 + 2 * c] = make_uint2(0, 0);
        }
    }
    __syncwarp();

    float c[2][16][4];
    #pragma unroll
    for (int nt = 0; nt < 16; nt++) {
        float2 b = *(const float2*)&bias[8 * nt + 2 * q];
        #pragma unroll
        for (int mt = 0; mt < 2; mt++) {
            c[mt][nt][0] = b.x; c[mt][nt][1] = b.y;
            c[mt][nt][2] = b.x; c[mt][nt][3] = b.y;
        }
    }
    #pragma unroll
    for (int kt = 0; kt < 8; kt++) {
        uint32_t a[2][4];
        #pragma unroll
        for (int mt = 0; mt < 2; mt++) {
            int r0 = (16*mt + g) * 68, r1 = (16*mt + 8 + g) * 68;
            a[mt][0] = buf[r0 + 8*kt + q];
            a[mt][1] = buf[r1 + 8*kt + q];
            a[mt][2] = buf[r0 + 8*kt + q + 4];
            a[mt][3] = buf[r1 + 8*kt + q + 4];
        }
        #pragma unroll
        for (int nt = 0; nt < 16; nt++) {
            uint32_t b0 = Wp[(8*nt+g)*68 + 8*kt + q];
            uint32_t b1 = Wp[(8*nt+g)*68 + 8*kt + q + 4];
            mma16(c[0][nt], a[0][0],a[0][1],a[0][2],a[0][3], b0, b1);
            mma16(c[1][nt], a[1][0],a[1][1],a[1][2],a[1][3], b0, b1);
        }
    }
    // store permuted f16 pairs
    #pragma unroll
    for (int nt = 0; nt < 16; nt++) {
        int word = (nt < 4)  ? (q*4 + nt)
                 : (nt < 8)  ? (16 + q*4 + (nt - 4))
                 :             (32 + q*8 + (nt - 8));
        #pragma unroll
        for (int mt = 0; mt < 2; mt++) {
            int n0 = nb + 16*mt + g, n1 = nb + 16*mt + 8 + g;
            if (n0 < Nn)
                ((uint32_t*)&g_P[(size_t)n0 * 128])[word] = h2pack(c[mt][nt][0], c[mt][nt][1]);
            if (n1 < Nn)
                ((uint32_t*)&g_P[(size_t)n1 * 128])[word] = h2pack(c[mt][nt][2], c[mt][nt][3]);
        }
    }
}

// ---------------------------------------------------------------------------
// Edge kernel: persistent, 8 warps x 32 edges, 2 CTAs/SM. mma.sync FP16.
// h1/em/h2 all pass layer-to-layer via in-register C->A packing; smem buf
// used only for ef staging and the scatter transpose.
// ---------------------------------------------------------------------------
#define OFF_W1  0            // [32 n][36 w]  -> 4608 B
#define OFF_W2  4608         // [128][20]     -> 10240 B
#define OFF_W3  14848        // [64][68]      -> 17408 B
#define OFF_W4  32256        // [128][36]     -> 18432 B
#define OFF_BE2 50688
#define OFF_BN2 51200
#define OFF_SCR 51712
#define WS_BYTES 4608        // per-warp buffer (ef f16 / nm f32)
#define SM_TOTAL (OFF_SCR + NWARP * WS_BYTES)   // 88576

__global__ void __launch_bounds__(TPB, 2) edge_mma_kernel(
    const float* __restrict__ ef,
    const int*   __restrict__ eidx,
    const float* __restrict__ We1,
    const float* __restrict__ We2,
    const float* __restrict__ be2,
    const float* __restrict__ Wn1,
    const float* __restrict__ Wn2,
    const float* __restrict__ bn2,
    float* __restrict__ out, int E, int ntiles)
{
    extern __shared__ char sm[];
    uint32_t* W1s = (uint32_t*)(sm + OFF_W1);
    uint32_t* W2s = (uint32_t*)(sm + OFF_W2);
    uint32_t* W3s = (uint32_t*)(sm + OFF_W3);
    uint32_t* W4s = (uint32_t*)(sm + OFF_W4);
    float* be2s = (float*)(sm + OFF_BE2);
    float* bn2s = (float*)(sm + OFF_BN2);

    const int tid = threadIdx.x;
    {
        const float* W = We1 + 256 * 32;
        for (int i = tid; i < 32 * 32; i += TPB) {
            int n = i >> 5, w = i & 31;
            W1s[n*36 + w] = h2pack(W[(2*w)*32 + n], W[(2*w+1)*32 + n]);
        }
        for (int i = tid; i < 128 * 16; i += TPB) {
            int n = i >> 4, w = i & 15;
            W2s[n*20 + w] = h2pack(We2[(2*w)*128 + n], We2[(2*w+1)*128 + n]);
        }
        const float* W3 = Wn1 + 128 * 64;
        for (int i = tid; i < 64 * 64; i += TPB) {
            int n = i >> 6, w = i & 63;
            W3s[n*68 + w] = h2pack(W3[(2*w)*64 + n], W3[(2*w+1)*64 + n]);
        }
        for (int i = tid; i < 128 * 32; i += TPB) {
            int n = i >> 5, w = i & 31;
            W4s[n*36 + w] = h2pack(Wn2[(2*w)*128 + n], Wn2[(2*w+1)*128 + n]);
        }
    }
    if (tid < 128) { be2s[tid] = be2[tid]; bn2s[tid] = bn2[tid]; }
    __syncthreads();

    const int lane = tid & 31, wid = tid >> 5;
    const int g = lane >> 2, q = lane & 3;
    const unsigned F = 0xFFFFFFFFu;
    uint32_t* buf  = (uint32_t*)(sm + OFF_SCR + wid * WS_BYTES);
    float*    buff = (float*)buf;

    for (int t = blockIdx.x; t < ntiles; t += gridDim.x) {
        const int eb = t * TILE_E + wid * 32;

        int sidx[4], didx[4];
        #pragma unroll
        for (int m = 0; m < 4; m++) {
            int r = eb + 16 * (m >> 1) + 8 * (m & 1) + g;
            r = (r < E) ? r : (E - 1);
            sidx[m] = eidx[r];
            didx[m] = eidx[E + r];
        }
        int rl = eb + lane; rl = (rl < E) ? rl : (E - 1);
        const int dl = eidx[E + rl];

        // ======== L1 init: c1 = pre1 =======================================
        float c1[2][4][4];
        #pragma unroll
        for (int m = 0; m < 4; m++) {
            const int mt = m >> 1, h = m & 1;
            uint4 us = *(const uint4*)&g_P[(size_t)sidx[m] * 128 + q * 8];
            uint4 ud = *(const uint4*)&g_P[(size_t)didx[m] * 128 + 32 + q * 8];
            const uint32_t* sw = (const uint32_t*)&us;
            const uint32_t* dw = (const uint32_t*)&ud;
            #pragma unroll
            for (int nt = 0; nt < 4; nt++) {
                float2 a = __half22float2(*(const __half2*)&sw[nt]);
                float2 b = __half22float2(*(const __half2*)&dw[nt]);
                c1[mt][nt][2*h]   = a.x + b.x;
                c1[mt][nt][2*h+1] = a.y + b.y;
            }
        }

        // ======== stage ef =================================================
        __syncwarp();
        #pragma unroll
        for (int i = 0; i < 16; i++) {
            int idx = i * 32 + lane;
            int row = idx >> 4, c16 = idx & 15;
            int r = eb + row; r = (r < E) ? r : (E - 1);
            float4 v = *(const float4*)&ef[(size_t)r * 64 + 4 * c16];
            uint2 w = { h2pack(v.x, v.y), h2pack(v.z, v.w) };
            *(uint2*)&buf[row * 36 + 2 * c16] = w;
        }
        __syncwarp();

        // ======== L1: K=64 -> 4 k16 chunks =================================
        #pragma unroll
        for (int kt = 0; kt < 4; kt++) {
            uint32_t a[2][4];
            #pragma unroll
            for (int mt = 0; mt < 2; mt++) {
                int r0 = (16*mt + g) * 36, r1 = (16*mt + 8 + g) * 36;
                a[mt][0] = buf[r0 + 8*kt + q];
                a[mt][1] = buf[r1 + 8*kt + q];
                a[mt][2] = buf[r0 + 8*kt + q + 4];
                a[mt][3] = buf[r1 + 8*kt + q + 4];
            }
            #pragma unroll
            for (int nt = 0; nt < 4; nt++) {
                uint32_t b0 = W1s[(8*nt+g)*36 + 8*kt + q];
                uint32_t b1 = W1s[(8*nt+g)*36 + 8*kt + q + 4];
                mma16(c1[0][nt], a[0][0],a[0][1],a[0][2],a[0][3], b0, b1);
                mma16(c1[1][nt], a[1][0],a[1][1],a[1][2],a[1][3], b0, b1);
            }
        }
        // ---- h1 C->A local packing (NO smem roundtrip) --------------------
        uint32_t h1a[2][2][4];
        #pragma unroll
        for (int kc = 0; kc < 2; kc++)
            #pragma unroll
            for (int mt = 0; mt < 2; mt++) {
                h1a[kc][mt][0] = h2relu(c1[mt][2*kc][0],   c1[mt][2*kc][1]);
                h1a[kc][mt][1] = h2relu(c1[mt][2*kc][2],   c1[mt][2*kc][3]);
                h1a[kc][mt][2] = h2relu(c1[mt][2*kc+1][0], c1[mt][2*kc+1][1]);
                h1a[kc][mt][3] = h2relu(c1[mt][2*kc+1][2], c1[mt][2*kc+1][3]);
            }

        // ========== L2+L3 fused ============================================
        float c3[2][8][4];
        #pragma unroll
        for (int m = 0; m < 4; m++) {
            const int mt = m >> 1, h = m & 1;
            const __half* Pp = &g_P[(size_t)didx[m] * 128 + 64 + q * 16];
            uint4 p0 = *(const uint4*)Pp;
            uint4 p1 = *(const uint4*)(Pp + 8);
            const uint32_t* w0 = (const uint32_t*)&p0;
            const uint32_t* w1 = (const uint32_t*)&p1;
            #pragma unroll
            for (int nt = 0; nt < 4; nt++) {
                float2 a = __half22float2(*(const __half2*)&w0[nt]);
                float2 b = __half22float2(*(const __half2*)&w1[nt]);
                c3[mt][nt][2*h]   = a.x;  c3[mt][nt][2*h+1]   = a.y;
                c3[mt][nt+4][2*h] = b.x;  c3[mt][nt+4][2*h+1] = b.y;
            }
        }
        #pragma unroll
        for (int ch = 0; ch < 4; ch++) {
            float c2[2][4][4];
            #pragma unroll
            for (int nt = 0; nt < 4; nt++) {
                float2 b = *(const float2*)&be2s[32*ch + 8*nt + 2*q];
                #pragma unroll
                for (int mt = 0; mt < 2; mt++) {
                    c2[mt][nt][0] = b.x; c2[mt][nt][1] = b.y;
                    c2[mt][nt][2] = b.x; c2[mt][nt][3] = b.y;
                }
            }
            #pragma unroll
            for (int kt = 0; kt < 2; kt++) {
                #pragma unroll
                for (int nt = 0; nt < 4; nt++) {
                    uint32_t b0 = W2s[(32*ch + 8*nt + g)*20 + 8*kt + q];
                    uint32_t b1 = W2s[(32*ch + 8*nt + g)*20 + 8*kt + q + 4];
                    mma16(c2[0][nt], h1a[kt][0][0],h1a[kt][0][1],h1a[kt][0][2],h1a[kt][0][3], b0, b1);
                    mma16(c2[1][nt], h1a[kt][1][0],h1a[kt][1][1],h1a[kt][1][2],h1a[kt][1][3], b0, b1);
                }
            }
            #pragma unroll
            for (int kc = 0; kc < 2; kc++) {
                uint32_t a[2][4];
                #pragma unroll
                for (int mt = 0; mt < 2; mt++) {
                    a[mt][0] = h2relu(c2[mt][2*kc][0],   c2[mt][2*kc][1]);
                    a[mt][1] = h2relu(c2[mt][2*kc][2],   c2[mt][2*kc][3]);
                    a[mt][2] = h2relu(c2[mt][2*kc+1][0], c2[mt][2*kc+1][1]);
                    a[mt][3] = h2relu(c2[mt][2*kc+1][2], c2[mt][2*kc+1][3]);
                }
                const int ktg = 2 * ch + kc;
                #pragma unroll
                for (int nt = 0; nt < 8; nt++) {
                    uint32_t b0 = W3s[(8*nt+g)*68 + 8*ktg + q];
                    uint32_t b1 = W3s[(8*nt+g)*68 + 8*ktg + q + 4];
                    mma16(c3[0][nt], a[0][0],a[0][1],a[0][2],a[0][3], b0, b1);
                    mma16(c3[1][nt], a[1][0],a[1][1],a[1][2],a[1][3], b0, b1);
                }
            }
        }

        // ---- h2 C->A local packing ----------------------------------------
        uint32_t h2a[4][2][4];
        #pragma unroll
        for (int kc = 0; kc < 4; kc++)
            #pragma unroll
            for (int mt = 0; mt < 2; mt++) {
                h2a[kc][mt][0] = h2relu(c3[mt][2*kc][0],   c3[mt][2*kc][1]);
                h2a[kc][mt][1] = h2relu(c3[mt][2*kc][2],   c3[mt][2*kc][3]);
                h2a[kc][mt][2] = h2relu(c3[mt][2*kc+1][0], c3[mt][2*kc+1][1]);
                h2a[kc][mt][3] = h2relu(c3[mt][2*kc+1][2], c3[mt][2*kc+1][3]);
            }

        // ============ L4 + smem transpose + coalesced red4 scatter =========
        #pragma unroll
        for (int n4 = 0; n4 < 4; n4++) {
            float c4[2][4][4];
            #pragma unroll
            for (int nt = 0; nt < 4; nt++) {
                float2 b = *(const float2*)&bn2s[32*n4 + 8*nt + 2*q];
                #pragma unroll
                for (int mt = 0; mt < 2; mt++) {
                    c4[mt][nt][0] = b.x; c4[mt][nt][1] = b.y;
                    c4[mt][nt][2] = b.x; c4[mt][nt][3] = b.y;
                }
            }
            #pragma unroll
            for (int kt = 0; kt < 4; kt++) {
                #pragma unroll
                for (int nt = 0; nt < 4; nt++) {
                    uint32_t b0 = W4s[(32*n4 + 8*nt + g)*36 + 8*kt + q];
                    uint32_t b1 = W4s[(32*n4 + 8*nt + g)*36 + 8*kt + q + 4];
                    mma16(c4[0][nt], h2a[kt][0][0],h2a[kt][0][1],h2a[kt][0][2],h2a[kt][0][3], b0, b1);
                    mma16(c4[1][nt], h2a[kt][1][0],h2a[kt][1][1],h2a[kt][1][2],h2a[kt][1][3], b0, b1);
                }
            }
            __syncwarp();
            #pragma unroll
            for (int mt = 0; mt < 2; mt++)
                #pragma unroll
                for (int nt = 0; nt < 4; nt++) {
                    const int col = 8 * nt + 2 * q;
                    float2 v0 = { fmaxf(c4[mt][nt][0], 0.f), fmaxf(c4[mt][nt][1], 0.f) };
                    float2 v1 = { fmaxf(c4[mt][nt][2], 0.f), fmaxf(c4[mt][nt][3], 0.f) };
                    *(float2*)&buff[(16*mt + g) * 36 + col]     = v0;
                    *(float2*)&buff[(16*mt + 8 + g) * 36 + col] = v1;
                }
            __syncwarp();
            #pragma unroll
            for (int i = 0; i < 8; i++) {
                int row = 4 * i + (lane >> 3);
                float4 v = *(const float4*)&buff[row * 36 + 4 * (lane & 7)];
                int dr = __shfl_sync(F, dl, row);
                if (eb + row < E)
                    red4(out + (size_t)dr * 128 + 32 * n4 + 4 * (lane & 7),
                         v.x, v.y, v.z, v.w);
            }
        }
    }
}

// ---------------------------------------------------------------------------
extern "C" void kernel_launch(void* const* d_in, const int* in_sizes, int n_in,
                              void* d_out, int out_size) {
    const float* nf  = (const float*)d_in[0];
    const float* ef  = (const float*)d_in[1];
    const int*   ei  = (const int*)  d_in[2];
    const float* We1 = (const float*)d_in[3];
    const float* be1 = (const float*)d_in[4];
    const float* We2 = (const float*)d_in[5];
    const float* be2 = (const float*)d_in[6];
    const float* Wn1 = (const float*)d_in[7];
    const float* bn1 = (const float*)d_in[8];
    const float* Wn2 = (const float*)d_in[9];
    const float* bn2 = (const float*)d_in[10];
    float* out = (float*)d_out;

    const int Nn = in_sizes[0] / 128;
    const int E  = in_sizes[2] / 2;
    const int ntiles = (E + TILE_E - 1) / TILE_E;

    cudaFuncSetAttribute(precompute_mma_kernel,
                         cudaFuncAttributeMaxDynamicSharedMemorySize, P_SMEM);
    precompute_mma_kernel<<<(Nn + 255) / 256, P_TPB, P_SMEM>>>(
        nf, We1, be1, Wn1, bn1, out, Nn);

    cudaFuncSetAttribute(edge_mma_kernel,
                         cudaFuncAttributeMaxDynamicSharedMemorySize, SM_TOTAL);
    edge_mma_kernel<<<EGRID, TPB, SM_TOTAL>>>(ef, ei, We1, We2, be2,
                                              Wn1, Wn2, bn2, out, E, ntiles);
}

// round 13
// speedup vs baseline: 1.0328x; 1.0084x over previous
#include <cuda_runtime.h>
#include <cuda_fp16.h>
#include <cstdint>

#define TPB 256
#define NWARP 8
#define TILE_E (NWARP * 32)
#define EGRID 304
#define MAXN 50000

// Per-node precomputed projections in FP16, COLUMN-PERMUTED:
// slice0 [0:32)  = nf@We1[0:128]+be1 (src)
// slice1 [32:64) = nf@We1[128:256]   (dst)
// slice2 [64:128)= nf@Wn1[0:128]+bn1 (pre2)
__device__ __align__(16) __half g_P[MAXN * 128];

// ------------------------------- helpers ----------------------------------
__device__ __forceinline__ uint32_t h2pack(float lo, float hi) {
    uint32_t r;  // cvt.rn.f16x2.f32 d, a, b -> d.hi = a, d.lo = b
    asm("cvt.rn.f16x2.f32 %0, %1, %2;" : "=r"(r) : "f"(hi), "f"(lo));
    return r;
}
__device__ __forceinline__ uint32_t h2relu(float c0, float c1) {
    return h2pack(fmaxf(c0, 0.f), fmaxf(c1, 0.f));
}
__device__ __forceinline__ void red4(float* p, float a, float b, float c, float d) {
    asm volatile("red.global.add.v4.f32 [%0], {%1,%2,%3,%4};"
                 :: "l"(p), "f"(a), "f"(b), "f"(c), "f"(d) : "memory");
}
// D(16x8,f32) += A(16x16,f16) @ B(16x8,f16)
__device__ __forceinline__ void mma16(float* c, uint32_t a0, uint32_t a1,
                                      uint32_t a2, uint32_t a3,
                                      uint32_t b0, uint32_t b1) {
    asm volatile("mma.sync.aligned.m16n8k16.row.col.f32.f16.f16.f32 "
                 "{%0,%1,%2,%3}, {%4,%5,%6,%7}, {%8,%9}, {%0,%1,%2,%3};"
                 : "+f"(c[0]), "+f"(c[1]), "+f"(c[2]), "+f"(c[3])
                 : "r"(a0), "r"(a1), "r"(a2), "r"(a3), "r"(b0), "r"(b1));
}

// ---------------------------------------------------------------------------
// Precompute via mma16: 32 nodes/warp, 4 warps (128 nodes/CTA), 2 CTAs/SM.
// Finer grid quantization halves the tail; per-node weight traffic unchanged.
// Fused out = node_features copy in the nf staging pass.
// ---------------------------------------------------------------------------
#define P_TPB 128
#define P_WSMEM 8704                 // per-warp nf buffer [32][68] words
#define P_OFF_B 34816                // bias after Wp [128][68] words
#define P_OFF_SCR 35328
#define P_SMEM (P_OFF_SCR + 4 * P_WSMEM)   // 70144

__global__ void __launch_bounds__(P_TPB, 2) precompute_mma_kernel(
    const float* __restrict__ nf,
    const float* __restrict__ We1,
    const float* __restrict__ be1,
    const float* __restrict__ Wn1,
    const float* __restrict__ bn1,
    float* __restrict__ out, int Nn)
{
    extern __shared__ char sm[];
    uint32_t* Wp = (uint32_t*)sm;                 // [128 n][68 w] f16x2
    float* bias  = (float*)(sm + P_OFF_B);        // [128]

    const int tid = threadIdx.x;
    for (int i = tid; i < 128 * 64; i += P_TPB) {
        int n = i >> 6, w = i & 63;
        float lo, hi;
        if (n < 32)      { lo = We1[(2*w)*32 + n];         hi = We1[(2*w+1)*32 + n]; }
        else if (n < 64) { lo = We1[(128+2*w)*32 + n-32];  hi = We1[(128+2*w+1)*32 + n-32]; }
        else             { lo = Wn1[(2*w)*64 + n-64];      hi = Wn1[(2*w+1)*64 + n-64]; }
        Wp[n*68 + w] = h2pack(lo, hi);
    }
    if (tid < 128)
        bias[tid] = (tid < 32) ? be1[tid] : ((tid < 64) ? 0.f : bn1[tid - 64]);
    __syncthreads();

    const int lane = tid & 31, wid = tid >> 5;
    const int g = lane >> 2, q = lane & 3;
    uint32_t* buf = (uint32_t*)(sm + P_OFF_SCR + wid * P_WSMEM);   // [32][68]

    const int nb = blockIdx.x * 128 + wid * 32;

    // stage nf rows (f32->f16x2) + fused out=nf copy
    #pragma unroll
    for (int it = 0; it < 32; it++) {
        int idx = it * 32 + lane;
        int row = idx >> 5, c = idx & 31;
        int n = nb + row;
        if (n < Nn) {
            float4 v = *(const float4*)&nf[(size_t)n * 128 + 4 * c];
            *(float4*)&out[(size_t)n * 128 + 4 * c] = v;
            uint2 w = { h2pack(v.x, v.y), h2pack(v.z, v.w) };
            *(uint2*)&buf[row * 68 + 2 * c] = w;
        } else {
            *(uint2*)&buf[row * 68 + 2 * c] = make_uint2(0, 0);
        }
    }
    __syncwarp();

    float c[2][16][4];
    #pragma unroll
    for (int nt = 0; nt < 16; nt++) {
        float2 b = *(const float2*)&bias[8 * nt + 2 * q];
        #pragma unroll
        for (int mt = 0; mt < 2; mt++) {
            c[mt][nt][0] = b.x; c[mt][nt][1] = b.y;
            c[mt][nt][2] = b.x; c[mt][nt][3] = b.y;
        }
    }
    #pragma unroll
    for (int kt = 0; kt < 8; kt++) {
        uint32_t a[2][4];
        #pragma unroll
        for (int mt = 0; mt < 2; mt++) {
            int r0 = (16*mt + g) * 68, r1 = (16*mt + 8 + g) * 68;
            a[mt][0] = buf[r0 + 8*kt + q];
            a[mt][1] = buf[r1 + 8*kt + q];
            a[mt][2] = buf[r0 + 8*kt + q + 4];
            a[mt][3] = buf[r1 + 8*kt + q + 4];
        }
        #pragma unroll
        for (int nt = 0; nt < 16; nt++) {
            uint32_t b0 = Wp[(8*nt+g)*68 + 8*kt + q];
            uint32_t b1 = Wp[(8*nt+g)*68 + 8*kt + q + 4];
            mma16(c[0][nt], a[0][0],a[0][1],a[0][2],a[0][3], b0, b1);
            mma16(c[1][nt], a[1][0],a[1][1],a[1][2],a[1][3], b0, b1);
        }
    }
    // store permuted f16 pairs
    #pragma unroll
    for (int nt = 0; nt < 16; nt++) {
        int word = (nt < 4)  ? (q*4 + nt)
                 : (nt < 8)  ? (16 + q*4 + (nt - 4))
                 :             (32 + q*8 + (nt - 8));
        #pragma unroll
        for (int mt = 0; mt < 2; mt++) {
            int n0 = nb + 16*mt + g, n1 = nb + 16*mt + 8 + g;
            if (n0 < Nn)
                ((uint32_t*)&g_P[(size_t)n0 * 128])[word] = h2pack(c[mt][nt][0], c[mt][nt][1]);
            if (n1 < Nn)
                ((uint32_t*)&g_P[(size_t)n1 * 128])[word] = h2pack(c[mt][nt][2], c[mt][nt][3]);
        }
    }
}

// ---------------------------------------------------------------------------
// Edge kernel: persistent, 8 warps x 32 edges, 2 CTAs/SM. mma.sync FP16.
// h1/em/h2 register-packed; scatter staged as f16x2 in a swizzled [32][16]
// word layout (conflict-free STS.32 / LDS.64), then coalesced red4.
// ---------------------------------------------------------------------------
#define OFF_W1  0            // [32 n][36 w]  -> 4608 B
#define OFF_W2  4608         // [128][20]     -> 10240 B
#define OFF_W3  14848        // [64][68]      -> 17408 B
#define OFF_W4  32256        // [128][36]     -> 18432 B
#define OFF_BE2 50688
#define OFF_BN2 51200
#define OFF_SCR 51712
#define WS_BYTES 4608        // per-warp buffer (ef f16 staging / nm f16 scatter)
#define SM_TOTAL (OFF_SCR + NWARP * WS_BYTES)   // 88576

__global__ void __launch_bounds__(TPB, 2) edge_mma_kernel(
    const float* __restrict__ ef,
    const int*   __restrict__ eidx,
    const float* __restrict__ We1,
    const float* __restrict__ We2,
    const float* __restrict__ be2,
    const float* __restrict__ Wn1,
    const float* __restrict__ Wn2,
    const float* __restrict__ bn2,
    float* __restrict__ out, int E, int ntiles)
{
    extern __shared__ char sm[];
    uint32_t* W1s = (uint32_t*)(sm + OFF_W1);
    uint32_t* W2s = (uint32_t*)(sm + OFF_W2);
    uint32_t* W3s = (uint32_t*)(sm + OFF_W3);
    uint32_t* W4s = (uint32_t*)(sm + OFF_W4);
    float* be2s = (float*)(sm + OFF_BE2);
    float* bn2s = (float*)(sm + OFF_BN2);

    const int tid = threadIdx.x;
    {
        const float* W = We1 + 256 * 32;
        for (int i = tid; i < 32 * 32; i += TPB) {
            int n = i >> 5, w = i & 31;
            W1s[n*36 + w] = h2pack(W[(2*w)*32 + n], W[(2*w+1)*32 + n]);
        }
        for (int i = tid; i < 128 * 16; i += TPB) {
            int n = i >> 4, w = i & 15;
            W2s[n*20 + w] = h2pack(We2[(2*w)*128 + n], We2[(2*w+1)*128 + n]);
        }
        const float* W3 = Wn1 + 128 * 64;
        for (int i = tid; i < 64 * 64; i += TPB) {
            int n = i >> 6, w = i & 63;
            W3s[n*68 + w] = h2pack(W3[(2*w)*64 + n], W3[(2*w+1)*64 + n]);
        }
        for (int i = tid; i < 128 * 32; i += TPB) {
            int n = i >> 5, w = i & 31;
            W4s[n*36 + w] = h2pack(Wn2[(2*w)*128 + n], Wn2[(2*w+1)*128 + n]);
        }
    }
    if (tid < 128) { be2s[tid] = be2[tid]; bn2s[tid] = bn2[tid]; }
    __syncthreads();

    const int lane = tid & 31, wid = tid >> 5;
    const int g = lane >> 2, q = lane & 3;
    const unsigned F = 0xFFFFFFFFu;
    uint32_t* buf = (uint32_t*)(sm + OFF_SCR + wid * WS_BYTES);

    for (int t = blockIdx.x; t < ntiles; t += gridDim.x) {
        const int eb = t * TILE_E + wid * 32;

        int sidx[4], didx[4];
        #pragma unroll
        for (int m = 0; m < 4; m++) {
            int r = eb + 16 * (m >> 1) + 8 * (m & 1) + g;
            r = (r < E) ? r : (E - 1);
            sidx[m] = eidx[r];
            didx[m] = eidx[E + r];
        }
        int rl = eb + lane; rl = (rl < E) ? rl : (E - 1);
        const int dl = eidx[E + rl];

        // ======== L1 init: c1 = pre1 =======================================
        float c1[2][4][4];
        #pragma unroll
        for (int m = 0; m < 4; m++) {
            const int mt = m >> 1, h = m & 1;
            uint4 us = *(const uint4*)&g_P[(size_t)sidx[m] * 128 + q * 8];
            uint4 ud = *(const uint4*)&g_P[(size_t)didx[m] * 128 + 32 + q * 8];
            const uint32_t* sw = (const uint32_t*)&us;
            const uint32_t* dw = (const uint32_t*)&ud;
            #pragma unroll
            for (int nt = 0; nt < 4; nt++) {
                float2 a = __half22float2(*(const __half2*)&sw[nt]);
                float2 b = __half22float2(*(const __half2*)&dw[nt]);
                c1[mt][nt][2*h]   = a.x + b.x;
                c1[mt][nt][2*h+1] = a.y + b.y;
            }
        }

        // ======== stage ef =================================================
        __syncwarp();
        #pragma unroll
        for (int i = 0; i < 16; i++) {
            int idx = i * 32 + lane;
            int row = idx >> 4, c16 = idx & 15;
            int r = eb + row; r = (r < E) ? r : (E - 1);
            float4 v = *(const float4*)&ef[(size_t)r * 64 + 4 * c16];
            uint2 w = { h2pack(v.x, v.y), h2pack(v.z, v.w) };
            *(uint2*)&buf[row * 36 + 2 * c16] = w;
        }
        __syncwarp();

        // ======== L1: K=64 -> 4 k16 chunks =================================
        #pragma unroll
        for (int kt = 0; kt < 4; kt++) {
            uint32_t a[2][4];
            #pragma unroll
            for (int mt = 0; mt < 2; mt++) {
                int r0 = (16*mt + g) * 36, r1 = (16*mt + 8 + g) * 36;
                a[mt][0] = buf[r0 + 8*kt + q];
                a[mt][1] = buf[r1 + 8*kt + q];
                a[mt][2] = buf[r0 + 8*kt + q + 4];
                a[mt][3] = buf[r1 + 8*kt + q + 4];
            }
            #pragma unroll
            for (int nt = 0; nt < 4; nt++) {
                uint32_t b0 = W1s[(8*nt+g)*36 + 8*kt + q];
                uint32_t b1 = W1s[(8*nt+g)*36 + 8*kt + q + 4];
                mma16(c1[0][nt], a[0][0],a[0][1],a[0][2],a[0][3], b0, b1);
                mma16(c1[1][nt], a[1][0],a[1][1],a[1][2],a[1][3], b0, b1);
            }
        }
        // ---- h1 C->A local packing ----------------------------------------
        uint32_t h1a[2][2][4];
        #pragma unroll
        for (int kc = 0; kc < 2; kc++)
            #pragma unroll
            for (int mt = 0; mt < 2; mt++) {
                h1a[kc][mt][0] = h2relu(c1[mt][2*kc][0],   c1[mt][2*kc][1]);
                h1a[kc][mt][1] = h2relu(c1[mt][2*kc][2],   c1[mt][2*kc][3]);
                h1a[kc][mt][2] = h2relu(c1[mt][2*kc+1][0], c1[mt][2*kc+1][1]);
                h1a[kc][mt][3] = h2relu(c1[mt][2*kc+1][2], c1[mt][2*kc+1][3]);
            }

        // ========== L2+L3 fused ============================================
        float c3[2][8][4];
        #pragma unroll
        for (int m = 0; m < 4; m++) {
            const int mt = m >> 1, h = m & 1;
            const __half* Pp = &g_P[(size_t)didx[m] * 128 + 64 + q * 16];
            uint4 p0 = *(const uint4*)Pp;
            uint4 p1 = *(const uint4*)(Pp + 8);
            const uint32_t* w0 = (const uint32_t*)&p0;
            const uint32_t* w1 = (const uint32_t*)&p1;
            #pragma unroll
            for (int nt = 0; nt < 4; nt++) {
                float2 a = __half22float2(*(const __half2*)&w0[nt]);
                float2 b = __half22float2(*(const __half2*)&w1[nt]);
                c3[mt][nt][2*h]   = a.x;  c3[mt][nt][2*h+1]   = a.y;
                c3[mt][nt+4][2*h] = b.x;  c3[mt][nt+4][2*h+1] = b.y;
            }
        }
        #pragma unroll
        for (int ch = 0; ch < 4; ch++) {
            float c2[2][4][4];
            #pragma unroll
            for (int nt = 0; nt < 4; nt++) {
                float2 b = *(const float2*)&be2s[32*ch + 8*nt + 2*q];
                #pragma unroll
                for (int mt = 0; mt < 2; mt++) {
                    c2[mt][nt][0] = b.x; c2[mt][nt][1] = b.y;
                    c2[mt][nt][2] = b.x; c2[mt][nt][3] = b.y;
                }
            }
            #pragma unroll
            for (int kt = 0; kt < 2; kt++) {
                #pragma unroll
                for (int nt = 0; nt < 4; nt++) {
                    uint32_t b0 = W2s[(32*ch + 8*nt + g)*20 + 8*kt + q];
                    uint32_t b1 = W2s[(32*ch + 8*nt + g)*20 + 8*kt + q + 4];
                    mma16(c2[0][nt], h1a[kt][0][0],h1a[kt][0][1],h1a[kt][0][2],h1a[kt][0][3], b0, b1);
                    mma16(c2[1][nt], h1a[kt][1][0],h1a[kt][1][1],h1a[kt][1][2],h1a[kt][1][3], b0, b1);
                }
            }
            #pragma unroll
            for (int kc = 0; kc < 2; kc++) {
                uint32_t a[2][4];
                #pragma unroll
                for (int mt = 0; mt < 2; mt++) {
                    a[mt][0] = h2relu(c2[mt][2*kc][0],   c2[mt][2*kc][1]);
                    a[mt][1] = h2relu(c2[mt][2*kc][2],   c2[mt][2*kc][3]);
                    a[mt][2] = h2relu(c2[mt][2*kc+1][0], c2[mt][2*kc+1][1]);
                    a[mt][3] = h2relu(c2[mt][2*kc+1][2], c2[mt][2*kc+1][3]);
                }
                const int ktg = 2 * ch + kc;
                #pragma unroll
                for (int nt = 0; nt < 8; nt++) {
                    uint32_t b0 = W3s[(8*nt+g)*68 + 8*ktg + q];
                    uint32_t b1 = W3s[(8*nt+g)*68 + 8*ktg + q + 4];
                    mma16(c3[0][nt], a[0][0],a[0][1],a[0][2],a[0][3], b0, b1);
                    mma16(c3[1][nt], a[1][0],a[1][1],a[1][2],a[1][3], b0, b1);
                }
            }
        }

        // ---- h2 C->A local packing ----------------------------------------
        uint32_t h2a[4][2][4];
        #pragma unroll
        for (int kc = 0; kc < 4; kc++)
            #pragma unroll
            for (int mt = 0; mt < 2; mt++) {
                h2a[kc][mt][0] = h2relu(c3[mt][2*kc][0],   c3[mt][2*kc][1]);
                h2a[kc][mt][1] = h2relu(c3[mt][2*kc][2],   c3[mt][2*kc][3]);
                h2a[kc][mt][2] = h2relu(c3[mt][2*kc+1][0], c3[mt][2*kc+1][1]);
                h2a[kc][mt][3] = h2relu(c3[mt][2*kc+1][2], c3[mt][2*kc+1][3]);
            }

        // ============ L4 + f16 swizzled transpose + coalesced red4 =========
        #pragma unroll
        for (int n4 = 0; n4 < 4; n4++) {
            float c4[2][4][4];
            #pragma unroll
            for (int nt = 0; nt < 4; nt++) {
                float2 b = *(const float2*)&bn2s[32*n4 + 8*nt + 2*q];
                #pragma unroll
                for (int mt = 0; mt < 2; mt++) {
                    c4[mt][nt][0] = b.x; c4[mt][nt][1] = b.y;
                    c4[mt][nt][2] = b.x; c4[mt][nt][3] = b.y;
                }
            }
            #pragma unroll
            for (int kt = 0; kt < 4; kt++) {
                #pragma unroll
                for (int nt = 0; nt < 4; nt++) {
                    uint32_t b0 = W4s[(32*n4 + 8*nt + g)*36 + 8*kt + q];
                    uint32_t b1 = W4s[(32*n4 + 8*nt + g)*36 + 8*kt + q + 4];
                    mma16(c4[0][nt], h2a[kt][0][0],h2a[kt][0][1],h2a[kt][0][2],h2a[kt][0][3], b0, b1);
                    mma16(c4[1][nt], h2a[kt][1][0],h2a[kt][1][1],h2a[kt][1][2],h2a[kt][1][3], b0, b1);
                }
            }
            __syncwarp();
            // store nm as f16x2 into swizzled [32 rows][16 words] layout
            #pragma unroll
            for (int mt = 0; mt < 2; mt++)
                #pragma unroll
                for (int nt = 0; nt < 4; nt++) {
                    uint32_t v0 = h2relu(c4[mt][nt][0], c4[mt][nt][1]);
                    uint32_t v1 = h2relu(c4[mt][nt][2], c4[mt][nt][3]);
                    const int w = 4*nt + q;
                    const int s = 4 * ((g >> 1) & 3);       // same for row and row+8
                    buf[(16*mt + g)     * 16 + ((w + s) & 15)] = v0;
                    buf[(16*mt + 8 + g) * 16 + ((w + s) & 15)] = v1;
                }
            __syncwarp();
            #pragma unroll
            for (int i = 0; i < 8; i++) {
                int row = 4 * i + (lane >> 3);
                int cc  = lane & 7;
                int w   = (2*cc + 4*((row >> 1) & 3)) & 15;
                uint2 vv = *(const uint2*)&buf[row * 16 + w];
                float2 f0 = __half22float2(*(const __half2*)&vv.x);
                float2 f1 = __half22float2(*(const __half2*)&vv.y);
                int dr = __shfl_sync(F, dl, row);
                if (eb + row < E)
                    red4(out + (size_t)dr * 128 + 32 * n4 + 4 * cc,
                         f0.x, f0.y, f1.x, f1.y);
            }
        }
    }
}

// ---------------------------------------------------------------------------
extern "C" void kernel_launch(void* const* d_in, const int* in_sizes, int n_in,
                              void* d_out, int out_size) {
    const float* nf  = (const float*)d_in[0];
    const float* ef  = (const float*)d_in[1];
    const int*   ei  = (const int*)  d_in[2];
    const float* We1 = (const float*)d_in[3];
    const float* be1 = (const float*)d_in[4];
    const float* We2 = (const float*)d_in[5];
    const float* be2 = (const float*)d_in[6];
    const float* Wn1 = (const float*)d_in[7];
    const float* bn1 = (const float*)d_in[8];
    const float* Wn2 = (const float*)d_in[9];
    const float* bn2 = (const float*)d_in[10];
    float* out = (float*)d_out;

    const int Nn = in_sizes[0] / 128;
    const int E  = in_sizes[2] / 2;
    const int ntiles = (E + TILE_E - 1) / TILE_E;

    cudaFuncSetAttribute(precompute_mma_kernel,
                         cudaFuncAttributeMaxDynamicSharedMemorySize, P_SMEM);
    precompute_mma_kernel<<<(Nn + 127) / 128, P_TPB, P_SMEM>>>(
        nf, We1, be1, Wn1, bn1, out, Nn);

    cudaFuncSetAttribute(edge_mma_kernel,
                         cudaFuncAttributeMaxDynamicSharedMemorySize, SM_TOTAL);
    edge_mma_kernel<<<EGRID, TPB, SM_TOTAL>>>(ef, ei, We1, We2, be2,
                                              Wn1, Wn2, bn2, out, E, ntiles);
}

// round 14
// speedup vs baseline: 1.0688x; 1.0348x over previous
#include <cuda_runtime.h>
#include <cuda_fp16.h>
#include <cstdint>

#define TPB 256
#define NWARP 8
#define TILE_E (NWARP * 32)
#define EGRID 304
#define MAXN 50000

// Per-node precomputed projections in FP16, COLUMN-PERMUTED:
// slice0 [0:32)  = nf@We1[0:128]+be1 (src)
// slice1 [32:64) = nf@We1[128:256]   (dst)
// slice2 [64:128)= nf@Wn1[0:128]+bn1 (pre2)
__device__ __align__(16) __half g_P[MAXN * 128];

// ------------------------------- helpers ----------------------------------
__device__ __forceinline__ uint32_t h2pack(float lo, float hi) {
    uint32_t r;  // cvt.rn.f16x2.f32 d, a, b -> d.hi = a, d.lo = b
    asm("cvt.rn.f16x2.f32 %0, %1, %2;" : "=r"(r) : "f"(hi), "f"(lo));
    return r;
}
__device__ __forceinline__ uint32_t h2relu(float c0, float c1) {
    return h2pack(fmaxf(c0, 0.f), fmaxf(c1, 0.f));
}
__device__ __forceinline__ void red4(float* p, float a, float b, float c, float d) {
    asm volatile("red.global.add.v4.f32 [%0], {%1,%2,%3,%4};"
                 :: "l"(p), "f"(a), "f"(b), "f"(c), "f"(d) : "memory");
}
// D(16x8,f32) += A(16x16,f16) @ B(16x8,f16)
__device__ __forceinline__ void mma16(float* c, uint32_t a0, uint32_t a1,
                                      uint32_t a2, uint32_t a3,
                                      uint32_t b0, uint32_t b1) {
    asm volatile("mma.sync.aligned.m16n8k16.row.col.f32.f16.f16.f32 "
                 "{%0,%1,%2,%3}, {%4,%5,%6,%7}, {%8,%9}, {%0,%1,%2,%3};"
                 : "+f"(c[0]), "+f"(c[1]), "+f"(c[2]), "+f"(c[3])
                 : "r"(a0), "r"(a1), "r"(a2), "r"(a3), "r"(b0), "r"(b1));
}

// ---------------------------------------------------------------------------
// Precompute via mma16 (R12 config: 32 nodes/warp, 8 warps, 256 nodes/CTA).
// Fused out = node_features copy in the nf staging pass.
// ---------------------------------------------------------------------------
#define P_TPB 256
#define P_WSMEM 8704                 // per-warp nf buffer [32][68] words
#define P_OFF_B 34816                // bias after Wp [128][68] words
#define P_OFF_SCR 35328
#define P_SMEM (P_OFF_SCR + 8 * P_WSMEM)   // 104960

__global__ void __launch_bounds__(P_TPB, 1) precompute_mma_kernel(
    const float* __restrict__ nf,
    const float* __restrict__ We1,
    const float* __restrict__ be1,
    const float* __restrict__ Wn1,
    const float* __restrict__ bn1,
    float* __restrict__ out, int Nn)
{
    extern __shared__ char sm[];
    uint32_t* Wp = (uint32_t*)sm;                 // [128 n][68 w] f16x2
    float* bias  = (float*)(sm + P_OFF_B);        // [128]

    const int tid = threadIdx.x;
    for (int i = tid; i < 128 * 64; i += P_TPB) {
        int n = i >> 6, w = i & 63;
        float lo, hi;
        if (n < 32)      { lo = We1[(2*w)*32 + n];         hi = We1[(2*w+1)*32 + n]; }
        else if (n < 64) { lo = We1[(128+2*w)*32 + n-32];  hi = We1[(128+2*w+1)*32 + n-32]; }
        else             { lo = Wn1[(2*w)*64 + n-64];      hi = Wn1[(2*w+1)*64 + n-64]; }
        Wp[n*68 + w] = h2pack(lo, hi);
    }
    if (tid < 128)
        bias[tid] = (tid < 32) ? be1[tid] : ((tid < 64) ? 0.f : bn1[tid - 64]);
    __syncthreads();

    const int lane = tid & 31, wid = tid >> 5;
    const int g = lane >> 2, q = lane & 3;
    uint32_t* buf = (uint32_t*)(sm + P_OFF_SCR + wid * P_WSMEM);   // [32][68]

    const int nb = blockIdx.x * 256 + wid * 32;

    // stage nf rows (f32->f16x2) + fused out=nf copy
    #pragma unroll
    for (int it = 0; it < 32; it++) {
        int idx = it * 32 + lane;
        int row = idx >> 5, c = idx & 31;
        int n = nb + row;
        if (n < Nn) {
            float4 v = *(const float4*)&nf[(size_t)n * 128 + 4 * c];
            *(float4*)&out[(size_t)n * 128 + 4 * c] = v;
            uint2 w = { h2pack(v.x, v.y), h2pack(v.z, v.w) };
            *(uint2*)&buf[row * 68 + 2 * c] = w;
        } else {
            *(uint2*)&buf[row * 68 + 2 * c] = make_uint2(0, 0);
        }
    }
    __syncwarp();

    float c[2][16][4];
    #pragma unroll
    for (int nt = 0; nt < 16; nt++) {
        float2 b = *(const float2*)&bias[8 * nt + 2 * q];
        #pragma unroll
        for (int mt = 0; mt < 2; mt++) {
            c[mt][nt][0] = b.x; c[mt][nt][1] = b.y;
            c[mt][nt][2] = b.x; c[mt][nt][3] = b.y;
        }
    }
    #pragma unroll
    for (int kt = 0; kt < 8; kt++) {
        uint32_t a[2][4];
        #pragma unroll
        for (int mt = 0; mt < 2; mt++) {
            int r0 = (16*mt + g) * 68, r1 = (16*mt + 8 + g) * 68;
            a[mt][0] = buf[r0 + 8*kt + q];
            a[mt][1] = buf[r1 + 8*kt + q];
            a[mt][2] = buf[r0 + 8*kt + q + 4];
            a[mt][3] = buf[r1 + 8*kt + q + 4];
        }
        #pragma unroll
        for (int nt = 0; nt < 16; nt++) {
            uint32_t b0 = Wp[(8*nt+g)*68 + 8*kt + q];
            uint32_t b1 = Wp[(8*nt+g)*68 + 8*kt + q + 4];
            mma16(c[0][nt], a[0][0],a[0][1],a[0][2],a[0][3], b0, b1);
            mma16(c[1][nt], a[1][0],a[1][1],a[1][2],a[1][3], b0, b1);
        }
    }
    // store permuted f16 pairs
    #pragma unroll
    for (int nt = 0; nt < 16; nt++) {
        int word = (nt < 4)  ? (q*4 + nt)
                 : (nt < 8)  ? (16 + q*4 + (nt - 4))
                 :             (32 + q*8 + (nt - 8));
        #pragma unroll
        for (int mt = 0; mt < 2; mt++) {
            int n0 = nb + 16*mt + g, n1 = nb + 16*mt + 8 + g;
            if (n0 < Nn)
                ((uint32_t*)&g_P[(size_t)n0 * 128])[word] = h2pack(c[mt][nt][0], c[mt][nt][1]);
            if (n1 < Nn)
                ((uint32_t*)&g_P[(size_t)n1 * 128])[word] = h2pack(c[mt][nt][2], c[mt][nt][3]);
        }
    }
}

// ---------------------------------------------------------------------------
// Edge kernel (R13 version): persistent, 8 warps x 32 edges, 2 CTAs/SM.
// h1/em/h2 register-packed; scatter staged as f16x2 in a swizzled [32][16]
// word layout (conflict-free STS.32 / LDS.64), then coalesced red4.
// ---------------------------------------------------------------------------
#define OFF_W1  0            // [32 n][36 w]  -> 4608 B
#define OFF_W2  4608         // [128][20]     -> 10240 B
#define OFF_W3  14848        // [64][68]      -> 17408 B
#define OFF_W4  32256        // [128][36]     -> 18432 B
#define OFF_BE2 50688
#define OFF_BN2 51200
#define OFF_SCR 51712
#define WS_BYTES 4608        // per-warp buffer (ef f16 staging / nm f16 scatter)
#define SM_TOTAL (OFF_SCR + NWARP * WS_BYTES)   // 88576

__global__ void __launch_bounds__(TPB, 2) edge_mma_kernel(
    const float* __restrict__ ef,
    const int*   __restrict__ eidx,
    const float* __restrict__ We1,
    const float* __restrict__ We2,
    const float* __restrict__ be2,
    const float* __restrict__ Wn1,
    const float* __restrict__ Wn2,
    const float* __restrict__ bn2,
    float* __restrict__ out, int E, int ntiles)
{
    extern __shared__ char sm[];
    uint32_t* W1s = (uint32_t*)(sm + OFF_W1);
    uint32_t* W2s = (uint32_t*)(sm + OFF_W2);
    uint32_t* W3s = (uint32_t*)(sm + OFF_W3);
    uint32_t* W4s = (uint32_t*)(sm + OFF_W4);
    float* be2s = (float*)(sm + OFF_BE2);
    float* bn2s = (float*)(sm + OFF_BN2);

    const int tid = threadIdx.x;
    {
        const float* W = We1 + 256 * 32;
        for (int i = tid; i < 32 * 32; i += TPB) {
            int n = i >> 5, w = i & 31;
            W1s[n*36 + w] = h2pack(W[(2*w)*32 + n], W[(2*w+1)*32 + n]);
        }
        for (int i = tid; i < 128 * 16; i += TPB) {
            int n = i >> 4, w = i & 15;
            W2s[n*20 + w] = h2pack(We2[(2*w)*128 + n], We2[(2*w+1)*128 + n]);
        }
        const float* W3 = Wn1 + 128 * 64;
        for (int i = tid; i < 64 * 64; i += TPB) {
            int n = i >> 6, w = i & 63;
            W3s[n*68 + w] = h2pack(W3[(2*w)*64 + n], W3[(2*w+1)*64 + n]);
        }
        for (int i = tid; i < 128 * 32; i += TPB) {
            int n = i >> 5, w = i & 31;
            W4s[n*36 + w] = h2pack(Wn2[(2*w)*128 + n], Wn2[(2*w+1)*128 + n]);
        }
    }
    if (tid < 128) { be2s[tid] = be2[tid]; bn2s[tid] = bn2[tid]; }
    __syncthreads();

    const int lane = tid & 31, wid = tid >> 5;
    const int g = lane >> 2, q = lane & 3;
    const unsigned F = 0xFFFFFFFFu;
    uint32_t* buf = (uint32_t*)(sm + OFF_SCR + wid * WS_BYTES);

    for (int t = blockIdx.x; t < ntiles; t += gridDim.x) {
        const int eb = t * TILE_E + wid * 32;

        int sidx[4], didx[4];
        #pragma unroll
        for (int m = 0; m < 4; m++) {
            int r = eb + 16 * (m >> 1) + 8 * (m & 1) + g;
            r = (r < E) ? r : (E - 1);
            sidx[m] = eidx[r];
            didx[m] = eidx[E + r];
        }
        int rl = eb + lane; rl = (rl < E) ? rl : (E - 1);
        const int dl = eidx[E + rl];

        // ======== L1 init: c1 = pre1 =======================================
        float c1[2][4][4];
        #pragma unroll
        for (int m = 0; m < 4; m++) {
            const int mt = m >> 1, h = m & 1;
            uint4 us = *(const uint4*)&g_P[(size_t)sidx[m] * 128 + q * 8];
            uint4 ud = *(const uint4*)&g_P[(size_t)didx[m] * 128 + 32 + q * 8];
            const uint32_t* sw = (const uint32_t*)&us;
            const uint32_t* dw = (const uint32_t*)&ud;
            #pragma unroll
            for (int nt = 0; nt < 4; nt++) {
                float2 a = __half22float2(*(const __half2*)&sw[nt]);
                float2 b = __half22float2(*(const __half2*)&dw[nt]);
                c1[mt][nt][2*h]   = a.x + b.x;
                c1[mt][nt][2*h+1] = a.y + b.y;
            }
        }

        // ======== stage ef =================================================
        __syncwarp();
        #pragma unroll
        for (int i = 0; i < 16; i++) {
            int idx = i * 32 + lane;
            int row = idx >> 4, c16 = idx & 15;
            int r = eb + row; r = (r < E) ? r : (E - 1);
            float4 v = *(const float4*)&ef[(size_t)r * 64 + 4 * c16];
            uint2 w = { h2pack(v.x, v.y), h2pack(v.z, v.w) };
            *(uint2*)&buf[row * 36 + 2 * c16] = w;
        }
        __syncwarp();

        // ======== L1: K=64 -> 4 k16 chunks =================================
        #pragma unroll
        for (int kt = 0; kt < 4; kt++) {
            uint32_t a[2][4];
            #pragma unroll
            for (int mt = 0; mt < 2; mt++) {
                int r0 = (16*mt + g) * 36, r1 = (16*mt + 8 + g) * 36;
                a[mt][0] = buf[r0 + 8*kt + q];
                a[mt][1] = buf[r1 + 8*kt + q];
                a[mt][2] = buf[r0 + 8*kt + q + 4];
                a[mt][3] = buf[r1 + 8*kt + q + 4];
            }
            #pragma unroll
            for (int nt = 0; nt < 4; nt++) {
                uint32_t b0 = W1s[(8*nt+g)*36 + 8*kt + q];
                uint32_t b1 = W1s[(8*nt+g)*36 + 8*kt + q + 4];
                mma16(c1[0][nt], a[0][0],a[0][1],a[0][2],a[0][3], b0, b1);
                mma16(c1[1][nt], a[1][0],a[1][1],a[1][2],a[1][3], b0, b1);
            }
        }
        // ---- h1 C->A local packing ----------------------------------------
        uint32_t h1a[2][2][4];
        #pragma unroll
        for (int kc = 0; kc < 2; kc++)
            #pragma unroll
            for (int mt = 0; mt < 2; mt++) {
                h1a[kc][mt][0] = h2relu(c1[mt][2*kc][0],   c1[mt][2*kc][1]);
                h1a[kc][mt][1] = h2relu(c1[mt][2*kc][2],   c1[mt][2*kc][3]);
                h1a[kc][mt][2] = h2relu(c1[mt][2*kc+1][0], c1[mt][2*kc+1][1]);
                h1a[kc][mt][3] = h2relu(c1[mt][2*kc+1][2], c1[mt][2*kc+1][3]);
            }

        // ========== L2+L3 fused ============================================
        float c3[2][8][4];
        #pragma unroll
        for (int m = 0; m < 4; m++) {
            const int mt = m >> 1, h = m & 1;
            const __half* Pp = &g_P[(size_t)didx[m] * 128 + 64 + q * 16];
            uint4 p0 = *(const uint4*)Pp;
            uint4 p1 = *(const uint4*)(Pp + 8);
            const uint32_t* w0 = (const uint32_t*)&p0;
            const uint32_t* w1 = (const uint32_t*)&p1;
            #pragma unroll
            for (int nt = 0; nt < 4; nt++) {
                float2 a = __half22float2(*(const __half2*)&w0[nt]);
                float2 b = __half22float2(*(const __half2*)&w1[nt]);
                c3[mt][nt][2*h]   = a.x;  c3[mt][nt][2*h+1]   = a.y;
                c3[mt][nt+4][2*h] = b.x;  c3[mt][nt+4][2*h+1] = b.y;
            }
        }
        #pragma unroll
        for (int ch = 0; ch < 4; ch++) {
            float c2[2][4][4];
            #pragma unroll
            for (int nt = 0; nt < 4; nt++) {
                float2 b = *(const float2*)&be2s[32*ch + 8*nt + 2*q];
                #pragma unroll
                for (int mt = 0; mt < 2; mt++) {
                    c2[mt][nt][0] = b.x; c2[mt][nt][1] = b.y;
                    c2[mt][nt][2] = b.x; c2[mt][nt][3] = b.y;
                }
            }
            #pragma unroll
            for (int kt = 0; kt < 2; kt++) {
                #pragma unroll
                for (int nt = 0; nt < 4; nt++) {
                    uint32_t b0 = W2s[(32*ch + 8*nt + g)*20 + 8*kt + q];
                    uint32_t b1 = W2s[(32*ch + 8*nt + g)*20 + 8*kt + q + 4];
                    mma16(c2[0][nt], h1a[kt][0][0],h1a[kt][0][1],h1a[kt][0][2],h1a[kt][0][3], b0, b1);
                    mma16(c2[1][nt], h1a[kt][1][0],h1a[kt][1][1],h1a[kt][1][2],h1a[kt][1][3], b0, b1);
                }
            }
            #pragma unroll
            for (int kc = 0; kc < 2; kc++) {
                uint32_t a[2][4];
                #pragma unroll
                for (int mt = 0; mt < 2; mt++) {
                    a[mt][0] = h2relu(c2[mt][2*kc][0],   c2[mt][2*kc][1]);
                    a[mt][1] = h2relu(c2[mt][2*kc][2],   c2[mt][2*kc][3]);
                    a[mt][2] = h2relu(c2[mt][2*kc+1][0], c2[mt][2*kc+1][1]);
                    a[mt][3] = h2relu(c2[mt][2*kc+1][2], c2[mt][2*kc+1][3]);
                }
                const int ktg = 2 * ch + kc;
                #pragma unroll
                for (int nt = 0; nt < 8; nt++) {
                    uint32_t b0 = W3s[(8*nt+g)*68 + 8*ktg + q];
                    uint32_t b1 = W3s[(8*nt+g)*68 + 8*ktg + q + 4];
                    mma16(c3[0][nt], a[0][0],a[0][1],a[0][2],a[0][3], b0, b1);
                    mma16(c3[1][nt], a[1][0],a[1][1],a[1][2],a[1][3], b0, b1);
                }
            }
        }

        // ---- h2 C->A local packing ----------------------------------------
        uint32_t h2a[4][2][4];
        #pragma unroll
        for (int kc = 0; kc < 4; kc++)
            #pragma unroll
            for (int mt = 0; mt < 2; mt++) {
                h2a[kc][mt][0] = h2relu(c3[mt][2*kc][0],   c3[mt][2*kc][1]);
                h2a[kc][mt][1] = h2relu(c3[mt][2*kc][2],   c3[mt][2*kc][3]);
                h2a[kc][mt][2] = h2relu(c3[mt][2*kc+1][0], c3[mt][2*kc+1][1]);
                h2a[kc][mt][3] = h2relu(c3[mt][2*kc+1][2], c3[mt][2*kc+1][3]);
            }

        // ============ L4 + f16 swizzled transpose + coalesced red4 =========
        #pragma unroll
        for (int n4 = 0; n4 < 4; n4++) {
            float c4[2][4][4];
            #pragma unroll
            for (int nt = 0; nt < 4; nt++) {
                float2 b = *(const float2*)&bn2s[32*n4 + 8*nt + 2*q];
                #pragma unroll
                for (int mt = 0; mt < 2; mt++) {
                    c4[mt][nt][0] = b.x; c4[mt][nt][1] = b.y;
                    c4[mt][nt][2] = b.x; c4[mt][nt][3] = b.y;
                }
            }
            #pragma unroll
            for (int kt = 0; kt < 4; kt++) {
                #pragma unroll
                for (int nt = 0; nt < 4; nt++) {
                    uint32_t b0 = W4s[(32*n4 + 8*nt + g)*36 + 8*kt + q];
                    uint32_t b1 = W4s[(32*n4 + 8*nt + g)*36 + 8*kt + q + 4];
                    mma16(c4[0][nt], h2a[kt][0][0],h2a[kt][0][1],h2a[kt][0][2],h2a[kt][0][3], b0, b1);
                    mma16(c4[1][nt], h2a[kt][1][0],h2a[kt][1][1],h2a[kt][1][2],h2a[kt][1][3], b0, b1);
                }
            }
            __syncwarp();
            // store nm as f16x2 into swizzled [32 rows][16 words] layout
            #pragma unroll
            for (int mt = 0; mt < 2; mt++)
                #pragma unroll
                for (int nt = 0; nt < 4; nt++) {
                    uint32_t v0 = h2relu(c4[mt][nt][0], c4[mt][nt][1]);
                    uint32_t v1 = h2relu(c4[mt][nt][2], c4[mt][nt][3]);
                    const int w = 4*nt + q;
                    const int s = 4 * ((g >> 1) & 3);       // same for row and row+8
                    buf[(16*mt + g)     * 16 + ((w + s) & 15)] = v0;
                    buf[(16*mt + 8 + g) * 16 + ((w + s) & 15)] = v1;
                }
            __syncwarp();
            #pragma unroll
            for (int i = 0; i < 8; i++) {
                int row = 4 * i + (lane >> 3);
                int cc  = lane & 7;
                int w   = (2*cc + 4*((row >> 1) & 3)) & 15;
                uint2 vv = *(const uint2*)&buf[row * 16 + w];
                float2 f0 = __half22float2(*(const __half2*)&vv.x);
                float2 f1 = __half22float2(*(const __half2*)&vv.y);
                int dr = __shfl_sync(F, dl, row);
                if (eb + row < E)
                    red4(out + (size_t)dr * 128 + 32 * n4 + 4 * cc,
                         f0.x, f0.y, f1.x, f1.y);
            }
        }
    }
}

// ---------------------------------------------------------------------------
extern "C" void kernel_launch(void* const* d_in, const int* in_sizes, int n_in,
                              void* d_out, int out_size) {
    const float* nf  = (const float*)d_in[0];
    const float* ef  = (const float*)d_in[1];
    const int*   ei  = (const int*)  d_in[2];
    const float* We1 = (const float*)d_in[3];
    const float* be1 = (const float*)d_in[4];
    const float* We2 = (const float*)d_in[5];
    const float* be2 = (const float*)d_in[6];
    const float* Wn1 = (const float*)d_in[7];
    const float* bn1 = (const float*)d_in[8];
    const float* Wn2 = (const float*)d_in[9];
    const float* bn2 = (const float*)d_in[10];
    float* out = (float*)d_out;

    const int Nn = in_sizes[0] / 128;
    const int E  = in_sizes[2] / 2;
    const int ntiles = (E + TILE_E - 1) / TILE_E;

    cudaFuncSetAttribute(precompute_mma_kernel,
                         cudaFuncAttributeMaxDynamicSharedMemorySize, P_SMEM);
    precompute_mma_kernel<<<(Nn + 255) / 256, P_TPB, P_SMEM>>>(
        nf, We1, be1, Wn1, bn1, out, Nn);

    cudaFuncSetAttribute(edge_mma_kernel,
                         cudaFuncAttributeMaxDynamicSharedMemorySize, SM_TOTAL);
    edge_mma_kernel<<<EGRID, TPB, SM_TOTAL>>>(ef, ei, We1, We2, be2,
                                              Wn1, Wn2, bn2, out, E, ntiles);
}

// round 15
// speedup vs baseline: 1.2302x; 1.1511x over previous
#include <cuda_runtime.h>
#include <cuda_fp16.h>
#include <cstdint>

#define TPB 256
#define NWARP 8
#define TILE_E (NWARP * 32)
#define EGRID 304
#define MAXN 50000

// Per-node precomputed projections in FP16, COLUMN-PERMUTED:
// slice0 [0:32)  = nf@We1[0:128]+be1 (src)
// slice1 [32:64) = nf@We1[128:256]   (dst)
// slice2 [64:128)= nf@Wn1[0:128]+bn1 (pre2)
__device__ __align__(16) __half g_P[MAXN * 128];

// Pre-packed weight images (bit-identical to the smem layouts, pitches incl.)
__device__ __align__(16) uint32_t g_Wpre[128 * 68];  // precompute [128 n][68 w]
__device__ __align__(16) uint32_t g_W1p[32 * 36];
__device__ __align__(16) uint32_t g_W2p[128 * 20];
__device__ __align__(16) uint32_t g_W3p[64 * 68];
__device__ __align__(16) uint32_t g_W4p[128 * 36];

// ------------------------------- helpers ----------------------------------
__device__ __forceinline__ uint32_t h2pack(float lo, float hi) {
    uint32_t r;  // cvt.rn.f16x2.f32 d, a, b -> d.hi = a, d.lo = b
    asm("cvt.rn.f16x2.f32 %0, %1, %2;" : "=r"(r) : "f"(hi), "f"(lo));
    return r;
}
__device__ __forceinline__ uint32_t h2relu(float c0, float c1) {
    return h2pack(fmaxf(c0, 0.f), fmaxf(c1, 0.f));
}
__device__ __forceinline__ void red4(float* p, float a, float b, float c, float d) {
    asm volatile("red.global.add.v4.f32 [%0], {%1,%2,%3,%4};"
                 :: "l"(p), "f"(a), "f"(b), "f"(c), "f"(d) : "memory");
}
// D(16x8,f32) += A(16x16,f16) @ B(16x8,f16)
__device__ __forceinline__ void mma16(float* c, uint32_t a0, uint32_t a1,
                                      uint32_t a2, uint32_t a3,
                                      uint32_t b0, uint32_t b1) {
    asm volatile("mma.sync.aligned.m16n8k16.row.col.f32.f16.f16.f32 "
                 "{%0,%1,%2,%3}, {%4,%5,%6,%7}, {%8,%9}, {%0,%1,%2,%3};"
                 : "+f"(c[0]), "+f"(c[1]), "+f"(c[2]), "+f"(c[3])
                 : "r"(a0), "r"(a1), "r"(a2), "r"(a3), "r"(b0), "r"(b1));
}

// ---------------------------------------------------------------------------
// Pack kernel: one-time scattered transpose + f16 pack of all weights into
// global images; downstream CTAs copy them coalesced.
// ---------------------------------------------------------------------------
__global__ void __launch_bounds__(256) pack_weights_kernel(
    const float* __restrict__ We1,
    const float* __restrict__ We2,
    const float* __restrict__ Wn1,
    const float* __restrict__ Wn2)
{
    const int tid = blockIdx.x * 256 + threadIdx.x;
    const int stride = gridDim.x * 256;

    for (int i = tid; i < 128 * 64; i += stride) {          // precompute block
        int n = i >> 6, w = i & 63;
        float lo, hi;
        if (n < 32)      { lo = We1[(2*w)*32 + n];         hi = We1[(2*w+1)*32 + n]; }
        else if (n < 64) { lo = We1[(128+2*w)*32 + n-32];  hi = We1[(128+2*w+1)*32 + n-32]; }
        else             { lo = Wn1[(2*w)*64 + n-64];      hi = Wn1[(2*w+1)*64 + n-64]; }
        g_Wpre[n*68 + w] = h2pack(lo, hi);
    }
    const float* W = We1 + 256 * 32;
    for (int i = tid; i < 32 * 32; i += stride) {
        int n = i >> 5, w = i & 31;
        g_W1p[n*36 + w] = h2pack(W[(2*w)*32 + n], W[(2*w+1)*32 + n]);
    }
    for (int i = tid; i < 128 * 16; i += stride) {
        int n = i >> 4, w = i & 15;
        g_W2p[n*20 + w] = h2pack(We2[(2*w)*128 + n], We2[(2*w+1)*128 + n]);
    }
    const float* W3 = Wn1 + 128 * 64;
    for (int i = tid; i < 64 * 64; i += stride) {
        int n = i >> 6, w = i & 63;
        g_W3p[n*68 + w] = h2pack(W3[(2*w)*64 + n], W3[(2*w+1)*64 + n]);
    }
    for (int i = tid; i < 128 * 32; i += stride) {
        int n = i >> 5, w = i & 31;
        g_W4p[n*36 + w] = h2pack(Wn2[(2*w)*128 + n], Wn2[(2*w+1)*128 + n]);
    }
}

// ---------------------------------------------------------------------------
// Precompute via mma16 (R12 config: 32 nodes/warp, 8 warps, 256 nodes/CTA).
// Weights copied coalesced from the packed image; fused out=nf copy.
// ---------------------------------------------------------------------------
#define P_TPB 256
#define P_WSMEM 8704                 // per-warp nf buffer [32][68] words
#define P_OFF_B 34816                // bias after Wp [128][68] words
#define P_OFF_SCR 35328
#define P_SMEM (P_OFF_SCR + 8 * P_WSMEM)   // 104960

__global__ void __launch_bounds__(P_TPB, 1) precompute_mma_kernel(
    const float* __restrict__ nf,
    const float* __restrict__ be1,
    const float* __restrict__ bn1,
    float* __restrict__ out, int Nn)
{
    extern __shared__ char sm[];
    uint32_t* Wp = (uint32_t*)sm;                 // [128 n][68 w] f16x2
    float* bias  = (float*)(sm + P_OFF_B);        // [128]

    const int tid = threadIdx.x;
    {
        const uint4* src = (const uint4*)g_Wpre;
        uint4* dst = (uint4*)Wp;
        for (int i = tid; i < (128 * 68) / 4; i += P_TPB) dst[i] = src[i];
    }
    if (tid < 128)
        bias[tid] = (tid < 32) ? be1[tid] : ((tid < 64) ? 0.f : bn1[tid - 64]);
    __syncthreads();

    const int lane = tid & 31, wid = tid >> 5;
    const int g = lane >> 2, q = lane & 3;
    uint32_t* buf = (uint32_t*)(sm + P_OFF_SCR + wid * P_WSMEM);   // [32][68]

    const int nb = blockIdx.x * 256 + wid * 32;

    // stage nf rows (f32->f16x2) + fused out=nf copy
    #pragma unroll
    for (int it = 0; it < 32; it++) {
        int idx = it * 32 + lane;
        int row = idx >> 5, c = idx & 31;
        int n = nb + row;
        if (n < Nn) {
            float4 v = *(const float4*)&nf[(size_t)n * 128 + 4 * c];
            *(float4*)&out[(size_t)n * 128 + 4 * c] = v;
            uint2 w = { h2pack(v.x, v.y), h2pack(v.z, v.w) };
            *(uint2*)&buf[row * 68 + 2 * c] = w;
        } else {
            *(uint2*)&buf[row * 68 + 2 * c] = make_uint2(0, 0);
        }
    }
    __syncwarp();

    float c[2][16][4];
    #pragma unroll
    for (int nt = 0; nt < 16; nt++) {
        float2 b = *(const float2*)&bias[8 * nt + 2 * q];
        #pragma unroll
        for (int mt = 0; mt < 2; mt++) {
            c[mt][nt][0] = b.x; c[mt][nt][1] = b.y;
            c[mt][nt][2] = b.x; c[mt][nt][3] = b.y;
        }
    }
    #pragma unroll
    for (int kt = 0; kt < 8; kt++) {
        uint32_t a[2][4];
        #pragma unroll
        for (int mt = 0; mt < 2; mt++) {
            int r0 = (16*mt + g) * 68, r1 = (16*mt + 8 + g) * 68;
            a[mt][0] = buf[r0 + 8*kt + q];
            a[mt][1] = buf[r1 + 8*kt + q];
            a[mt][2] = buf[r0 + 8*kt + q + 4];
            a[mt][3] = buf[r1 + 8*kt + q + 4];
        }
        #pragma unroll
        for (int nt = 0; nt < 16; nt++) {
            uint32_t b0 = Wp[(8*nt+g)*68 + 8*kt + q];
            uint32_t b1 = Wp[(8*nt+g)*68 + 8*kt + q + 4];
            mma16(c[0][nt], a[0][0],a[0][1],a[0][2],a[0][3], b0, b1);
            mma16(c[1][nt], a[1][0],a[1][1],a[1][2],a[1][3], b0, b1);
        }
    }
    // store permuted f16 pairs
    #pragma unroll
    for (int nt = 0; nt < 16; nt++) {
        int word = (nt < 4)  ? (q*4 + nt)
                 : (nt < 8)  ? (16 + q*4 + (nt - 4))
                 :             (32 + q*8 + (nt - 8));
        #pragma unroll
        for (int mt = 0; mt < 2; mt++) {
            int n0 = nb + 16*mt + g, n1 = nb + 16*mt + 8 + g;
            if (n0 < Nn)
                ((uint32_t*)&g_P[(size_t)n0 * 128])[word] = h2pack(c[mt][nt][0], c[mt][nt][1]);
            if (n1 < Nn)
                ((uint32_t*)&g_P[(size_t)n1 * 128])[word] = h2pack(c[mt][nt][2], c[mt][nt][3]);
        }
    }
}

// ---------------------------------------------------------------------------
// Edge kernel (R13 math): persistent, 8 warps x 32 edges, 2 CTAs/SM.
// Weights copied coalesced from packed images. h1/em/h2 register-packed;
// scatter staged f16x2 in swizzled [32][16] layout -> coalesced red4.
// ---------------------------------------------------------------------------
#define OFF_W1  0            // [32 n][36 w]  -> 4608 B
#define OFF_W2  4608         // [128][20]     -> 10240 B
#define OFF_W3  14848        // [64][68]      -> 17408 B
#define OFF_W4  32256        // [128][36]     -> 18432 B
#define OFF_BE2 50688
#define OFF_BN2 51200
#define OFF_SCR 51712
#define WS_BYTES 4608        // per-warp buffer (ef f16 staging / nm f16 scatter)
#define SM_TOTAL (OFF_SCR + NWARP * WS_BYTES)   // 88576

__global__ void __launch_bounds__(TPB, 2) edge_mma_kernel(
    const float* __restrict__ ef,
    const int*   __restrict__ eidx,
    const float* __restrict__ be2,
    const float* __restrict__ bn2,
    float* __restrict__ out, int E, int ntiles)
{
    extern __shared__ char sm[];
    uint32_t* W1s = (uint32_t*)(sm + OFF_W1);
    uint32_t* W2s = (uint32_t*)(sm + OFF_W2);
    uint32_t* W3s = (uint32_t*)(sm + OFF_W3);
    uint32_t* W4s = (uint32_t*)(sm + OFF_W4);
    float* be2s = (float*)(sm + OFF_BE2);
    float* bn2s = (float*)(sm + OFF_BN2);

    const int tid = threadIdx.x;
    {
        uint4* dst = (uint4*)(sm + OFF_W1);          // W1..W4 contiguous images
        const uint4* s1 = (const uint4*)g_W1p;
        const uint4* s2 = (const uint4*)g_W2p;
        const uint4* s3 = (const uint4*)g_W3p;
        const uint4* s4 = (const uint4*)g_W4p;
        for (int i = tid; i < 288;  i += TPB) ((uint4*)(sm + OFF_W1))[i] = s1[i];
        for (int i = tid; i < 640;  i += TPB) ((uint4*)(sm + OFF_W2))[i] = s2[i];
        for (int i = tid; i < 1088; i += TPB) ((uint4*)(sm + OFF_W3))[i] = s3[i];
        for (int i = tid; i < 1152; i += TPB) ((uint4*)(sm + OFF_W4))[i] = s4[i];
        (void)dst;
    }
    if (tid < 128) { be2s[tid] = be2[tid]; bn2s[tid] = bn2[tid]; }
    __syncthreads();

    const int lane = tid & 31, wid = tid >> 5;
    const int g = lane >> 2, q = lane & 3;
    const unsigned F = 0xFFFFFFFFu;
    uint32_t* buf = (uint32_t*)(sm + OFF_SCR + wid * WS_BYTES);

    for (int t = blockIdx.x; t < ntiles; t += gridDim.x) {
        const int eb = t * TILE_E + wid * 32;

        int sidx[4], didx[4];
        #pragma unroll
        for (int m = 0; m < 4; m++) {
            int r = eb + 16 * (m >> 1) + 8 * (m & 1) + g;
            r = (r < E) ? r : (E - 1);
            sidx[m] = eidx[r];
            didx[m] = eidx[E + r];
        }
        int rl = eb + lane; rl = (rl < E) ? rl : (E - 1);
        const int dl = eidx[E + rl];

        // ======== L1 init: c1 = pre1 =======================================
        float c1[2][4][4];
        #pragma unroll
        for (int m = 0; m < 4; m++) {
            const int mt = m >> 1, h = m & 1;
            uint4 us = *(const uint4*)&g_P[(size_t)sidx[m] * 128 + q * 8];
            uint4 ud = *(const uint4*)&g_P[(size_t)didx[m] * 128 + 32 + q * 8];
            const uint32_t* sw = (const uint32_t*)&us;
            const uint32_t* dw = (const uint32_t*)&ud;
            #pragma unroll
            for (int nt = 0; nt < 4; nt++) {
                float2 a = __half22float2(*(const __half2*)&sw[nt]);
                float2 b = __half22float2(*(const __half2*)&dw[nt]);
                c1[mt][nt][2*h]   = a.x + b.x;
                c1[mt][nt][2*h+1] = a.y + b.y;
            }
        }

        // ======== stage ef =================================================
        __syncwarp();
        #pragma unroll
        for (int i = 0; i < 16; i++) {
            int idx = i * 32 + lane;
            int row = idx >> 4, c16 = idx & 15;
            int r = eb + row; r = (r < E) ? r : (E - 1);
            float4 v = *(const float4*)&ef[(size_t)r * 64 + 4 * c16];
            uint2 w = { h2pack(v.x, v.y), h2pack(v.z, v.w) };
            *(uint2*)&buf[row * 36 + 2 * c16] = w;
        }
        __syncwarp();

        // ======== L1: K=64 -> 4 k16 chunks =================================
        #pragma unroll
        for (int kt = 0; kt < 4; kt++) {
            uint32_t a[2][4];
            #pragma unroll
            for (int mt = 0; mt < 2; mt++) {
                int r0 = (16*mt + g) * 36, r1 = (16*mt + 8 + g) * 36;
                a[mt][0] = buf[r0 + 8*kt + q];
                a[mt][1] = buf[r1 + 8*kt + q];
                a[mt][2] = buf[r0 + 8*kt + q + 4];
                a[mt][3] = buf[r1 + 8*kt + q + 4];
            }
            #pragma unroll
            for (int nt = 0; nt < 4; nt++) {
                uint32_t b0 = W1s[(8*nt+g)*36 + 8*kt + q];
                uint32_t b1 = W1s[(8*nt+g)*36 + 8*kt + q + 4];
                mma16(c1[0][nt], a[0][0],a[0][1],a[0][2],a[0][3], b0, b1);
                mma16(c1[1][nt], a[1][0],a[1][1],a[1][2],a[1][3], b0, b1);
            }
        }
        // ---- h1 C->A local packing ----------------------------------------
        uint32_t h1a[2][2][4];
        #pragma unroll
        for (int kc = 0; kc < 2; kc++)
            #pragma unroll
            for (int mt = 0; mt < 2; mt++) {
                h1a[kc][mt][0] = h2relu(c1[mt][2*kc][0],   c1[mt][2*kc][1]);
                h1a[kc][mt][1] = h2relu(c1[mt][2*kc][2],   c1[mt][2*kc][3]);
                h1a[kc][mt][2] = h2relu(c1[mt][2*kc+1][0], c1[mt][2*kc+1][1]);
                h1a[kc][mt][3] = h2relu(c1[mt][2*kc+1][2], c1[mt][2*kc+1][3]);
            }

        // ========== L2+L3 fused ============================================
        float c3[2][8][4];
        #pragma unroll
        for (int m = 0; m < 4; m++) {
            const int mt = m >> 1, h = m & 1;
            const __half* Pp = &g_P[(size_t)didx[m] * 128 + 64 + q * 16];
            uint4 p0 = *(const uint4*)Pp;
            uint4 p1 = *(const uint4*)(Pp + 8);
            const uint32_t* w0 = (const uint32_t*)&p0;
            const uint32_t* w1 = (const uint32_t*)&p1;
            #pragma unroll
            for (int nt = 0; nt < 4; nt++) {
                float2 a = __half22float2(*(const __half2*)&w0[nt]);
                float2 b = __half22float2(*(const __half2*)&w1[nt]);
                c3[mt][nt][2*h]   = a.x;  c3[mt][nt][2*h+1]   = a.y;
                c3[mt][nt+4][2*h] = b.x;  c3[mt][nt+4][2*h+1] = b.y;
            }
        }
        #pragma unroll
        for (int ch = 0; ch < 4; ch++) {
            float c2[2][4][4];
            #pragma unroll
            for (int nt = 0; nt < 4; nt++) {
                float2 b = *(const float2*)&be2s[32*ch + 8*nt + 2*q];
                #pragma unroll
                for (int mt = 0; mt < 2; mt++) {
                    c2[mt][nt][0] = b.x; c2[mt][nt][1] = b.y;
                    c2[mt][nt][2] = b.x; c2[mt][nt][3] = b.y;
                }
            }
            #pragma unroll
            for (int kt = 0; kt < 2; kt++) {
                #pragma unroll
                for (int nt = 0; nt < 4; nt++) {
                    uint32_t b0 = W2s[(32*ch + 8*nt + g)*20 + 8*kt + q];
                    uint32_t b1 = W2s[(32*ch + 8*nt + g)*20 + 8*kt + q + 4];
                    mma16(c2[0][nt], h1a[kt][0][0],h1a[kt][0][1],h1a[kt][0][2],h1a[kt][0][3], b0, b1);
                    mma16(c2[1][nt], h1a[kt][1][0],h1a[kt][1][1],h1a[kt][1][2],h1a[kt][1][3], b0, b1);
                }
            }
            #pragma unroll
            for (int kc = 0; kc < 2; kc++) {
                uint32_t a[2][4];
                #pragma unroll
                for (int mt = 0; mt < 2; mt++) {
                    a[mt][0] = h2relu(c2[mt][2*kc][0],   c2[mt][2*kc][1]);
                    a[mt][1] = h2relu(c2[mt][2*kc][2],   c2[mt][2*kc][3]);
                    a[mt][2] = h2relu(c2[mt][2*kc+1][0], c2[mt][2*kc+1][1]);
                    a[mt][3] = h2relu(c2[mt][2*kc+1][2], c2[mt][2*kc+1][3]);
                }
                const int ktg = 2 * ch + kc;
                #pragma unroll
                for (int nt = 0; nt < 8; nt++) {
                    uint32_t b0 = W3s[(8*nt+g)*68 + 8*ktg + q];
                    uint32_t b1 = W3s[(8*nt+g)*68 + 8*ktg + q + 4];
                    mma16(c3[0][nt], a[0][0],a[0][1],a[0][2],a[0][3], b0, b1);
                    mma16(c3[1][nt], a[1][0],a[1][1],a[1][2],a[1][3], b0, b1);
                }
            }
        }

        // ---- h2 C->A local packing ----------------------------------------
        uint32_t h2a[4][2][4];
        #pragma unroll
        for (int kc = 0; kc < 4; kc++)
            #pragma unroll
            for (int mt = 0; mt < 2; mt++) {
                h2a[kc][mt][0] = h2relu(c3[mt][2*kc][0],   c3[mt][2*kc][1]);
                h2a[kc][mt][1] = h2relu(c3[mt][2*kc][2],   c3[mt][2*kc][3]);
                h2a[kc][mt][2] = h2relu(c3[mt][2*kc+1][0], c3[mt][2*kc+1][1]);
                h2a[kc][mt][3] = h2relu(c3[mt][2*kc+1][2], c3[mt][2*kc+1][3]);
            }

        // ============ L4 + f16 swizzled transpose + coalesced red4 =========
        #pragma unroll
        for (int n4 = 0; n4 < 4; n4++) {
            float c4[2][4][4];
            #pragma unroll
            for (int nt = 0; nt < 4; nt++) {
                float2 b = *(const float2*)&bn2s[32*n4 + 8*nt + 2*q];
                #pragma unroll
                for (int mt = 0; mt < 2; mt++) {
                    c4[mt][nt][0] = b.x; c4[mt][nt][1] = b.y;
                    c4[mt][nt][2] = b.x; c4[mt][nt][3] = b.y;
                }
            }
            #pragma unroll
            for (int kt = 0; kt < 4; kt++) {
                #pragma unroll
                for (int nt = 0; nt < 4; nt++) {
                    uint32_t b0 = W4s[(32*n4 + 8*nt + g)*36 + 8*kt + q];
                    uint32_t b1 = W4s[(32*n4 + 8*nt + g)*36 + 8*kt + q + 4];
                    mma16(c4[0][nt], h2a[kt][0][0],h2a[kt][0][1],h2a[kt][0][2],h2a[kt][0][3], b0, b1);
                    mma16(c4[1][nt], h2a[kt][1][0],h2a[kt][1][1],h2a[kt][1][2],h2a[kt][1][3], b0, b1);
                }
            }
            __syncwarp();
            // store nm as f16x2 into swizzled [32 rows][16 words] layout
            #pragma unroll
            for (int mt = 0; mt < 2; mt++)
                #pragma unroll
                for (int nt = 0; nt < 4; nt++) {
                    uint32_t v0 = h2relu(c4[mt][nt][0], c4[mt][nt][1]);
                    uint32_t v1 = h2relu(c4[mt][nt][2], c4[mt][nt][3]);
                    const int w = 4*nt + q;
                    const int s = 4 * ((g >> 1) & 3);       // same for row and row+8
                    buf[(16*mt + g)     * 16 + ((w + s) & 15)] = v0;
                    buf[(16*mt + 8 + g) * 16 + ((w + s) & 15)] = v1;
                }
            __syncwarp();
            #pragma unroll
            for (int i = 0; i < 8; i++) {
                int row = 4 * i + (lane >> 3);
                int cc  = lane & 7;
                int w   = (2*cc + 4*((row >> 1) & 3)) & 15;
                uint2 vv = *(const uint2*)&buf[row * 16 + w];
                float2 f0 = __half22float2(*(const __half2*)&vv.x);
                float2 f1 = __half22float2(*(const __half2*)&vv.y);
                int dr = __shfl_sync(F, dl, row);
                if (eb + row < E)
                    red4(out + (size_t)dr * 128 + 32 * n4 + 4 * cc,
                         f0.x, f0.y, f1.x, f1.y);
            }
        }
    }
}

// ---------------------------------------------------------------------------
extern "C" void kernel_launch(void* const* d_in, const int* in_sizes, int n_in,
                              void* d_out, int out_size) {
    const float* nf  = (const float*)d_in[0];
    const float* ef  = (const float*)d_in[1];
    const int*   ei  = (const int*)  d_in[2];
    const float* We1 = (const float*)d_in[3];
    const float* be1 = (const float*)d_in[4];
    const float* We2 = (const float*)d_in[5];
    const float* be2 = (const float*)d_in[6];
    const float* Wn1 = (const float*)d_in[7];
    const float* bn1 = (const float*)d_in[8];
    const float* Wn2 = (const float*)d_in[9];
    const float* bn2 = (const float*)d_in[10];
    float* out = (float*)d_out;

    const int Nn = in_sizes[0] / 128;
    const int E  = in_sizes[2] / 2;
    const int ntiles = (E + TILE_E - 1) / TILE_E;

    pack_weights_kernel<<<48, 256>>>(We1, We2, Wn1, Wn2);

    cudaFuncSetAttribute(precompute_mma_kernel,
                         cudaFuncAttributeMaxDynamicSharedMemorySize, P_SMEM);
    precompute_mma_kernel<<<(Nn + 255) / 256, P_TPB, P_SMEM>>>(
        nf, be1, bn1, out, Nn);

    cudaFuncSetAttribute(edge_mma_kernel,
                         cudaFuncAttributeMaxDynamicSharedMemorySize, SM_TOTAL);
    edge_mma_kernel<<<EGRID, TPB, SM_TOTAL>>>(ef, ei, be2, bn2, out, E, ntiles);
}